// round 1
// baseline (speedup 1.0000x reference)
#include <cuda_runtime.h>
#include <cuda_bf16.h>
#include <math_constants.h>

// Problem constants
#define BATCH 4
#define LEN   1024
#define DMODEL 1024
#define HEADS 16
#define HDIM  64
#define SCALE 0.03125f   // 1/sqrt(1024)

// Attention tiling
#define QT 8             // query rows per block (== warps per block)
#define ATHREADS 256

// Projection GEMM tiling
#define BM 64
#define BN 64
#define BK 16

// Scratch for attention output (allocs are forbidden; device global is allowed)
__device__ float g_O[BATCH * LEN * DMODEL];

// ---------------------------------------------------------------------------
// Kernel 1: attention. One block handles (b, h, 8 query rows).
// Full score row (L=1024) kept in smem; two-pass softmax; coalesced P·V.
// ---------------------------------------------------------------------------
__global__ __launch_bounds__(ATHREADS)
void attn_kernel(const float* __restrict__ Q,
                 const float* __restrict__ K,
                 const float* __restrict__ V)
{
    __shared__ float sQ[QT][HDIM];      // 2 KB
    __shared__ float sS[QT][LEN];       // 32 KB

    const int t  = threadIdx.x;
    const int b  = blockIdx.z;
    const int h  = blockIdx.y;
    const int q0 = blockIdx.x * QT;

    const size_t base = (size_t)b * LEN * DMODEL + (size_t)h * HDIM;

    // ---- load Q tile ----
    for (int i = t; i < QT * HDIM; i += ATHREADS) {
        int qi = i / HDIM, d = i % HDIM;
        sQ[qi][d] = Q[base + (size_t)(q0 + qi) * DMODEL + d];
    }
    __syncthreads();

    // ---- phase 1: scores S = (Q K^T) * scale ----
    // idx layout: k fastest -> consecutive lanes share qi (broadcast sQ row)
    for (int idx = t; idx < QT * LEN; idx += ATHREADS) {
        const int k  = idx & (LEN - 1);
        const int qi = idx >> 10;
        const float4* kp = reinterpret_cast<const float4*>(K + base + (size_t)k * DMODEL);
        const float4* qp = reinterpret_cast<const float4*>(&sQ[qi][0]);
        float s = 0.f;
        #pragma unroll
        for (int d4 = 0; d4 < HDIM / 4; d4++) {
            float4 kv = kp[d4];
            float4 qv = qp[d4];
            s += qv.x * kv.x + qv.y * kv.y + qv.z * kv.z + qv.w * kv.w;
        }
        sS[qi][k] = s * SCALE;
    }
    __syncthreads();

    // ---- phase 2: softmax, one warp per row ----
    {
        const int w    = t >> 5;   // row
        const int lane = t & 31;
        float m = -CUDART_INF_F;
        for (int k = lane; k < LEN; k += 32) m = fmaxf(m, sS[w][k]);
        #pragma unroll
        for (int o = 16; o; o >>= 1) m = fmaxf(m, __shfl_xor_sync(0xffffffffu, m, o));

        float sum = 0.f;
        for (int k = lane; k < LEN; k += 32) {
            float e = __expf(sS[w][k] - m);
            sS[w][k] = e;
            sum += e;
        }
        #pragma unroll
        for (int o = 16; o; o >>= 1) sum += __shfl_xor_sync(0xffffffffu, sum, o);

        const float inv = 1.0f / sum;
        for (int k = lane; k < LEN; k += 32) sS[w][k] *= inv;
    }
    __syncthreads();

    // ---- phase 3: O = P V  (coalesced over d) ----
    for (int idx = t; idx < QT * HDIM; idx += ATHREADS) {
        const int d  = idx & (HDIM - 1);
        const int qi = idx >> 6;
        const float* vp = V + base + d;
        const float* p  = &sS[qi][0];
        float a0 = 0.f, a1 = 0.f, a2 = 0.f, a3 = 0.f;
        #pragma unroll 4
        for (int k = 0; k < LEN; k += 4) {
            a0 += p[k + 0] * vp[(size_t)(k + 0) * DMODEL];
            a1 += p[k + 1] * vp[(size_t)(k + 1) * DMODEL];
            a2 += p[k + 2] * vp[(size_t)(k + 2) * DMODEL];
            a3 += p[k + 3] * vp[(size_t)(k + 3) * DMODEL];
        }
        g_O[base + (size_t)(q0 + qi) * DMODEL + d] = (a0 + a1) + (a2 + a3);
    }
}

// ---------------------------------------------------------------------------
// Kernel 2: out = g_O @ W^T + bias.  A[m][k], W[n][k] both k-contiguous.
// 64x64 block tile, BK=16, 4x4 microtile per thread.
// ---------------------------------------------------------------------------
__global__ __launch_bounds__(256)
void proj_kernel(const float* __restrict__ W,
                 const float* __restrict__ bias,
                 float* __restrict__ out)
{
    __shared__ float sA[BK][BM + 4];
    __shared__ float sW[BK][BN + 4];

    const int tx = threadIdx.x & 15;   // n direction
    const int ty = threadIdx.x >> 4;   // m direction
    const int m0 = blockIdx.y * BM;
    const int n0 = blockIdx.x * BN;

    float acc[4][4] = {};

    for (int k0 = 0; k0 < DMODEL; k0 += BK) {
        for (int i = threadIdx.x; i < BM * BK; i += 256) {
            int r = i >> 4, c = i & 15;
            sA[c][r] = g_O[(size_t)(m0 + r) * DMODEL + k0 + c];
        }
        for (int i = threadIdx.x; i < BN * BK; i += 256) {
            int r = i >> 4, c = i & 15;
            sW[c][r] = W[(size_t)(n0 + r) * DMODEL + k0 + c];
        }
        __syncthreads();

        #pragma unroll
        for (int kk = 0; kk < BK; kk++) {
            float a[4], w[4];
            #pragma unroll
            for (int i = 0; i < 4; i++) a[i] = sA[kk][ty * 4 + i];
            #pragma unroll
            for (int j = 0; j < 4; j++) w[j] = sW[kk][tx * 4 + j];
            #pragma unroll
            for (int i = 0; i < 4; i++)
                #pragma unroll
                for (int j = 0; j < 4; j++)
                    acc[i][j] += a[i] * w[j];
        }
        __syncthreads();
    }

    #pragma unroll
    for (int i = 0; i < 4; i++) {
        const int m = m0 + ty * 4 + i;
        #pragma unroll
        for (int j = 0; j < 4; j++) {
            const int n = n0 + tx * 4 + j;
            out[(size_t)m * DMODEL + n] = acc[i][j] + bias[n];
        }
    }
}

// ---------------------------------------------------------------------------
extern "C" void kernel_launch(void* const* d_in, const int* in_sizes, int n_in,
                              void* d_out, int out_size)
{
    const float* Q  = (const float*)d_in[0];
    const float* K  = (const float*)d_in[1];
    const float* V  = (const float*)d_in[2];
    const float* W  = (const float*)d_in[3];
    const float* bi = (const float*)d_in[4];
    // d_in[5] = mask (scalar 0) -> ignored, matching reference's `if mask:` branch
    float* out = (float*)d_out;

    dim3 agrid(LEN / QT, HEADS, BATCH);
    attn_kernel<<<agrid, ATHREADS>>>(Q, K, V);

    dim3 pgrid(DMODEL / BN, (BATCH * LEN) / BM);
    proj_kernel<<<pgrid, 256>>>(W, bi, out);
}

// round 2
// speedup vs baseline: 6.6665x; 6.6665x over previous
#include <cuda_runtime.h>
#include <cuda_bf16.h>
#include <math_constants.h>

// Problem constants
#define BATCH 4
#define LEN   1024
#define DMODEL 1024
#define HEADS 16
#define HDIM  64
#define SCALE 0.03125f   // 1/sqrt(1024)

// Attention tiling: Q tile 64 rows, K/V tile 32 rows, 256 threads (16x16)
#define TQ 64
#define TK 32

// Projection GEMM tiling: 128x128 block tile, BK=16, 8x8 microtile, 256 threads
#define PBM 128
#define PBN 128
#define PBK 16

// Scratch for attention output (device global; allocs forbidden)
__device__ float g_O[BATCH * LEN * DMODEL];

__device__ __forceinline__ float hgroup_max(float v) {
    // reduce across the 16-lane tx group (groups align to half-warps)
    #pragma unroll
    for (int o = 8; o; o >>= 1) v = fmaxf(v, __shfl_xor_sync(0xffffffffu, v, o));
    return v;
}
__device__ __forceinline__ float hgroup_sum(float v) {
    #pragma unroll
    for (int o = 8; o; o >>= 1) v += __shfl_xor_sync(0xffffffffu, v, o);
    return v;
}

// ---------------------------------------------------------------------------
// Flash-style attention. Block = (b, h, 64 query rows). 256 threads.
// thread grid 16x16: ty = t>>4 (rows), tx = t&15.
// S micro: rows ty*4+i (4), cols tx*2+j (2)  over a 64x32 S tile
// O micro: rows ty*4+i (4), dcols tx*4+j (4) over 64x64 O
// ---------------------------------------------------------------------------
__global__ __launch_bounds__(256)
void attn_kernel(const float* __restrict__ Q,
                 const float* __restrict__ K,
                 const float* __restrict__ V)
{
    __shared__ float sQt[HDIM][TQ + 4];   // [d][r]  64x68
    __shared__ float sKt[HDIM][TK + 2];   // [d][c]  64x34
    __shared__ float sV [TK][HDIM + 4];   // [k][d]  32x68
    __shared__ float sP [TQ][TK + 4];     // [r][k]  64x36

    const int t  = threadIdx.x;
    const int tx = t & 15;
    const int ty = t >> 4;
    const int b  = blockIdx.z;
    const int h  = blockIdx.y;
    const int q0 = blockIdx.x * TQ;

    const size_t base = (size_t)b * LEN * DMODEL + (size_t)h * HDIM;

    // ---- load Q tile transposed: sQt[d][r] ----
    {
        const int r = t >> 2;          // 0..63
        const int q = t & 3;           // 0..3
        const float* qrow = Q + base + (size_t)(q0 + r) * DMODEL;
        #pragma unroll
        for (int u = 0; u < 4; u++) {
            const int d = (q + 4 * u) * 4;
            float4 v4 = *reinterpret_cast<const float4*>(qrow + d);
            sQt[d + 0][r] = v4.x;
            sQt[d + 1][r] = v4.y;
            sQt[d + 2][r] = v4.z;
            sQt[d + 3][r] = v4.w;
        }
    }

    float m[4], l[4], O[4][4];
    #pragma unroll
    for (int i = 0; i < 4; i++) {
        m[i] = -CUDART_INF_F;
        l[i] = 0.f;
        #pragma unroll
        for (int j = 0; j < 4; j++) O[i][j] = 0.f;
    }

    const int kc = t >> 3;   // 0..31 (row within K/V tile)
    const int kq = t & 7;    // 0..7

    for (int kt = 0; kt < LEN / TK; kt++) {
        const int krow = kt * TK + kc;
        // ---- load K tile transposed, V tile row-major ----
        {
            const float* krp = K + base + (size_t)krow * DMODEL;
            const float* vrp = V + base + (size_t)krow * DMODEL;
            #pragma unroll
            for (int u = 0; u < 2; u++) {
                const int d = (kq + 8 * u) * 4;
                float4 kv = *reinterpret_cast<const float4*>(krp + d);
                sKt[d + 0][kc] = kv.x;
                sKt[d + 1][kc] = kv.y;
                sKt[d + 2][kc] = kv.z;
                sKt[d + 3][kc] = kv.w;
                float4 vv = *reinterpret_cast<const float4*>(vrp + d);
                *reinterpret_cast<float4*>(&sV[kc][d]) = vv;
            }
        }
        __syncthreads();

        // ---- S = Q K^T * scale (64x32 tile, 4x2 per thread) ----
        float s[4][2] = {};
        #pragma unroll 8
        for (int d = 0; d < HDIM; d++) {
            float4 a = *reinterpret_cast<const float4*>(&sQt[d][ty * 4]);
            float2 bb = *reinterpret_cast<const float2*>(&sKt[d][tx * 2]);
            s[0][0] += a.x * bb.x;  s[0][1] += a.x * bb.y;
            s[1][0] += a.y * bb.x;  s[1][1] += a.y * bb.y;
            s[2][0] += a.z * bb.x;  s[2][1] += a.z * bb.y;
            s[3][0] += a.w * bb.x;  s[3][1] += a.w * bb.y;
        }

        // ---- online softmax update ----
        #pragma unroll
        for (int i = 0; i < 4; i++) {
            s[i][0] *= SCALE; s[i][1] *= SCALE;
            float rmax = fmaxf(s[i][0], s[i][1]);
            rmax = hgroup_max(rmax);
            float mnew = fmaxf(m[i], rmax);
            float corr = __expf(m[i] - mnew);     // exp(-inf)=0 on first tile
            float p0 = __expf(s[i][0] - mnew);
            float p1 = __expf(s[i][1] - mnew);
            float rsum = hgroup_sum(p0 + p1);
            l[i] = l[i] * corr + rsum;
            m[i] = mnew;
            #pragma unroll
            for (int j = 0; j < 4; j++) O[i][j] *= corr;
            *reinterpret_cast<float2*>(&sP[ty * 4 + i][tx * 2]) = make_float2(p0, p1);
        }
        __syncthreads();

        // ---- O += P V (32-step k loop, 4x4 per thread) ----
        #pragma unroll 8
        for (int k = 0; k < TK; k++) {
            float4 bv = *reinterpret_cast<const float4*>(&sV[k][tx * 4]);
            #pragma unroll
            for (int i = 0; i < 4; i++) {
                float a = sP[ty * 4 + i][k];
                O[i][0] += a * bv.x;
                O[i][1] += a * bv.y;
                O[i][2] += a * bv.z;
                O[i][3] += a * bv.w;
            }
        }
        __syncthreads();   // before next tile overwrites sKt/sV/sP
    }

    // ---- finalize and write ----
    #pragma unroll
    for (int i = 0; i < 4; i++) {
        const float inv = 1.0f / l[i];
        float4 o4 = make_float4(O[i][0] * inv, O[i][1] * inv, O[i][2] * inv, O[i][3] * inv);
        *reinterpret_cast<float4*>(
            &g_O[base + (size_t)(q0 + ty * 4 + i) * DMODEL + tx * 4]) = o4;
    }
}

// ---------------------------------------------------------------------------
// Projection: out = g_O @ W^T + bias. A[m][k], W[n][k] both k-contiguous.
// 128x128 tile, BK=16, 8x8 microtile per thread (256 threads, 16x16 grid).
// ---------------------------------------------------------------------------
__global__ __launch_bounds__(256)
void proj_kernel(const float* __restrict__ W,
                 const float* __restrict__ bias,
                 float* __restrict__ out)
{
    __shared__ float sAt[PBK][PBM + 4];   // [k][m]
    __shared__ float sWt[PBK][PBN + 4];   // [k][n]

    const int t  = threadIdx.x;
    const int tx = t & 15;
    const int ty = t >> 4;
    const int m0 = blockIdx.y * PBM;
    const int n0 = blockIdx.x * PBN;

    const int lr = t >> 1;   // 0..127 (row within tile)
    const int lq = t & 1;    // 0..1

    float acc[8][8] = {};

    for (int k0 = 0; k0 < DMODEL; k0 += PBK) {
        // load A tile (128 x 16), transposed into sAt
        {
            const float* ap = g_O + (size_t)(m0 + lr) * DMODEL + k0;
            const float* wp = W   + (size_t)(n0 + lr) * DMODEL + k0;
            #pragma unroll
            for (int u = 0; u < 2; u++) {
                const int k = (lq + 2 * u) * 4;
                float4 av = *reinterpret_cast<const float4*>(ap + k);
                sAt[k + 0][lr] = av.x;
                sAt[k + 1][lr] = av.y;
                sAt[k + 2][lr] = av.z;
                sAt[k + 3][lr] = av.w;
                float4 wv = *reinterpret_cast<const float4*>(wp + k);
                sWt[k + 0][lr] = wv.x;
                sWt[k + 1][lr] = wv.y;
                sWt[k + 2][lr] = wv.z;
                sWt[k + 3][lr] = wv.w;
            }
        }
        __syncthreads();

        #pragma unroll
        for (int kk = 0; kk < PBK; kk++) {
            float a[8], b[8];
            *reinterpret_cast<float4*>(a)     = *reinterpret_cast<const float4*>(&sAt[kk][ty * 8]);
            *reinterpret_cast<float4*>(a + 4) = *reinterpret_cast<const float4*>(&sAt[kk][ty * 8 + 4]);
            *reinterpret_cast<float4*>(b)     = *reinterpret_cast<const float4*>(&sWt[kk][tx * 8]);
            *reinterpret_cast<float4*>(b + 4) = *reinterpret_cast<const float4*>(&sWt[kk][tx * 8 + 4]);
            #pragma unroll
            for (int i = 0; i < 8; i++)
                #pragma unroll
                for (int j = 0; j < 8; j++)
                    acc[i][j] += a[i] * b[j];
        }
        __syncthreads();
    }

    // epilogue with bias
    float4 b0 = *reinterpret_cast<const float4*>(bias + n0 + tx * 8);
    float4 b1 = *reinterpret_cast<const float4*>(bias + n0 + tx * 8 + 4);
    #pragma unroll
    for (int i = 0; i < 8; i++) {
        const size_t row = (size_t)(m0 + ty * 8 + i) * DMODEL;
        float4 o0 = make_float4(acc[i][0] + b0.x, acc[i][1] + b0.y,
                                acc[i][2] + b0.z, acc[i][3] + b0.w);
        float4 o1 = make_float4(acc[i][4] + b1.x, acc[i][5] + b1.y,
                                acc[i][6] + b1.z, acc[i][7] + b1.w);
        *reinterpret_cast<float4*>(out + row + n0 + tx * 8)     = o0;
        *reinterpret_cast<float4*>(out + row + n0 + tx * 8 + 4) = o1;
    }
}

// ---------------------------------------------------------------------------
extern "C" void kernel_launch(void* const* d_in, const int* in_sizes, int n_in,
                              void* d_out, int out_size)
{
    const float* Q  = (const float*)d_in[0];
    const float* K  = (const float*)d_in[1];
    const float* V  = (const float*)d_in[2];
    const float* W  = (const float*)d_in[3];
    const float* bi = (const float*)d_in[4];
    float* out = (float*)d_out;

    dim3 agrid(LEN / TQ, HEADS, BATCH);
    attn_kernel<<<agrid, 256>>>(Q, K, V);

    dim3 pgrid(DMODEL / PBN, (BATCH * LEN) / PBM);
    proj_kernel<<<pgrid, 256>>>(W, bi, out);
}

// round 3
// speedup vs baseline: 15.4013x; 2.3102x over previous
#include <cuda_runtime.h>
#include <cuda_bf16.h>
#include <math_constants.h>
#include <cstdint>

// Problem constants
#define BATCH  4
#define LEN    1024
#define DMODEL 1024
#define HEADS  16
#define HDIM   64
#define SCALE  0.03125f   // 1/sqrt(1024)

// Attention tiling: 64 q-rows per block, K/V tile = 32, 4 warps
#define TQ 64
#define TK 32

// Scratch for attention output (device global; allocs forbidden)
__device__ float g_O[BATCH * LEN * DMODEL];

// ---- helpers -------------------------------------------------------------

__device__ __forceinline__ float tf32f(float x) {
    uint32_t u;
    asm("cvt.rna.tf32.f32 %0, %1;" : "=r"(u) : "f"(x));
    return __uint_as_float(u);
}

// D = A(16x8,row) * B(8x8,col) + D, tf32 inputs, f32 accum
__device__ __forceinline__ void mma_tf32(float c[4],
                                         uint32_t a0, uint32_t a1, uint32_t a2, uint32_t a3,
                                         uint32_t b0, uint32_t b1) {
    asm volatile(
        "mma.sync.aligned.m16n8k8.row.col.f32.tf32.tf32.f32 "
        "{%0,%1,%2,%3}, {%4,%5,%6,%7}, {%8,%9}, {%0,%1,%2,%3};"
        : "+f"(c[0]), "+f"(c[1]), "+f"(c[2]), "+f"(c[3])
        : "r"(a0), "r"(a1), "r"(a2), "r"(a3), "r"(b0), "r"(b1));
}

#define CVT4(dst, r, d, v4)            \
    dst[r][(d) + 0] = tf32f(v4.x);     \
    dst[r][(d) + 1] = tf32f(v4.y);     \
    dst[r][(d) + 2] = tf32f(v4.z);     \
    dst[r][(d) + 3] = tf32f(v4.w);

// ---------------------------------------------------------------------------
// Flash-style attention with tf32 MMA.
// Block = (b, h, 64 q rows), 128 threads (4 warps), warp w owns rows w*16..w*16+15.
// Fragment bank-padding: stride%32==4 for row-indexed A/B frags (4g+tig distinct),
// stride%32==8 for sV (8tig+g distinct).
// ---------------------------------------------------------------------------
__global__ __launch_bounds__(128)
void attn_kernel(const float* __restrict__ Q,
                 const float* __restrict__ K,
                 const float* __restrict__ V)
{
    __shared__ float sQ[TQ][68];   // Q tile (tf32 bits)      17.0 KB
    __shared__ float sK[TK][68];   // K tile (tf32 bits)       8.5 KB
    __shared__ float sV[TK][72];   // V tile (tf32 bits)       9.0 KB
    __shared__ float sP[TQ][36];   // P tile (tf32 bits)       9.0 KB

    const int t    = threadIdx.x;
    const int lane = t & 31;
    const int wid  = t >> 5;
    const int g    = lane >> 2;    // group (row within frag)
    const int tig  = lane & 3;     // thread-in-group
    const int warpM = wid * 16;

    const int b  = blockIdx.z;
    const int h  = blockIdx.y;
    const int q0 = blockIdx.x * TQ;
    const size_t base = (size_t)b * LEN * DMODEL + (size_t)h * HDIM;

    // ---- load Q tile (2 threads/row, 8 float4 each), tf32-round on store ----
    {
        const int r = t >> 1, half = t & 1;
        const float* qp = Q + base + (size_t)(q0 + r) * DMODEL + half * 32;
        #pragma unroll
        for (int u = 0; u < 8; u++) {
            float4 v4 = *reinterpret_cast<const float4*>(qp + u * 4);
            const int d = half * 32 + u * 4;
            CVT4(sQ, r, d, v4);
        }
    }

    float m0 = -CUDART_INF_F, m1 = -CUDART_INF_F, l0 = 0.f, l1 = 0.f;
    float o[8][4] = {};            // O accum: 8 d-ntiles x 4 regs (16x64 per warp)

    const int kr = t >> 2;         // 0..31 (row within K/V tile)
    const int kq = t & 3;          // 0..3

    for (int kt = 0; kt < LEN / TK; kt++) {
        __syncthreads();           // prev PV done before overwriting sK/sV
        {
            const float* kp = K + base + (size_t)(kt * TK + kr) * DMODEL + kq * 16;
            const float* vp = V + base + (size_t)(kt * TK + kr) * DMODEL + kq * 16;
            #pragma unroll
            for (int u = 0; u < 4; u++) {
                float4 kv = *reinterpret_cast<const float4*>(kp + u * 4);
                const int d = kq * 16 + u * 4;
                CVT4(sK, kr, d, kv);
                float4 vv = *reinterpret_cast<const float4*>(vp + u * 4);
                CVT4(sV, kr, d, vv);
            }
        }
        __syncthreads();

        // ---- S = Q K^T : 16x32 per warp = 4 ntiles, 8 k-steps ----
        float s[4][4] = {};
        #pragma unroll
        for (int k0 = 0; k0 < HDIM; k0 += 8) {
            uint32_t a0 = __float_as_uint(sQ[warpM + g    ][k0 + tig    ]);
            uint32_t a1 = __float_as_uint(sQ[warpM + g + 8][k0 + tig    ]);
            uint32_t a2 = __float_as_uint(sQ[warpM + g    ][k0 + tig + 4]);
            uint32_t a3 = __float_as_uint(sQ[warpM + g + 8][k0 + tig + 4]);
            #pragma unroll
            for (int nt = 0; nt < 4; nt++) {
                uint32_t b0 = __float_as_uint(sK[nt * 8 + g][k0 + tig    ]);
                uint32_t b1 = __float_as_uint(sK[nt * 8 + g][k0 + tig + 4]);
                mma_tf32(s[nt], a0, a1, a2, a3, b0, b1);
            }
        }

        // ---- online softmax (rows g and g+8 of warp slab) ----
        float rmax0 = -CUDART_INF_F, rmax1 = -CUDART_INF_F;
        #pragma unroll
        for (int nt = 0; nt < 4; nt++) {
            #pragma unroll
            for (int j = 0; j < 4; j++) s[nt][j] *= SCALE;
            rmax0 = fmaxf(rmax0, fmaxf(s[nt][0], s[nt][1]));
            rmax1 = fmaxf(rmax1, fmaxf(s[nt][2], s[nt][3]));
        }
        #pragma unroll
        for (int off = 1; off < 4; off <<= 1) {
            rmax0 = fmaxf(rmax0, __shfl_xor_sync(0xffffffffu, rmax0, off));
            rmax1 = fmaxf(rmax1, __shfl_xor_sync(0xffffffffu, rmax1, off));
        }
        const float mn0 = fmaxf(m0, rmax0), mn1 = fmaxf(m1, rmax1);
        const float c0 = __expf(m0 - mn0), c1 = __expf(m1 - mn1);
        m0 = mn0; m1 = mn1;

        float sum0 = 0.f, sum1 = 0.f;
        #pragma unroll
        for (int nt = 0; nt < 4; nt++) {
            float p00 = __expf(s[nt][0] - m0);
            float p01 = __expf(s[nt][1] - m0);
            float p10 = __expf(s[nt][2] - m1);
            float p11 = __expf(s[nt][3] - m1);
            sum0 += p00 + p01;
            sum1 += p10 + p11;
            *reinterpret_cast<float2*>(&sP[warpM + g    ][nt * 8 + 2 * tig]) =
                make_float2(tf32f(p00), tf32f(p01));
            *reinterpret_cast<float2*>(&sP[warpM + g + 8][nt * 8 + 2 * tig]) =
                make_float2(tf32f(p10), tf32f(p11));
        }
        #pragma unroll
        for (int off = 1; off < 4; off <<= 1) {
            sum0 += __shfl_xor_sync(0xffffffffu, sum0, off);
            sum1 += __shfl_xor_sync(0xffffffffu, sum1, off);
        }
        l0 = l0 * c0 + sum0;
        l1 = l1 * c1 + sum1;
        #pragma unroll
        for (int nt = 0; nt < 8; nt++) {
            o[nt][0] *= c0; o[nt][1] *= c0;
            o[nt][2] *= c1; o[nt][3] *= c1;
        }
        __syncwarp();  // P stores visible to other lanes of this warp

        // ---- O += P V : A = P (16x32), B = V (32x64), 4 k-steps, 8 d-ntiles ----
        #pragma unroll
        for (int k0 = 0; k0 < TK; k0 += 8) {
            uint32_t a0 = __float_as_uint(sP[warpM + g    ][k0 + tig    ]);
            uint32_t a1 = __float_as_uint(sP[warpM + g + 8][k0 + tig    ]);
            uint32_t a2 = __float_as_uint(sP[warpM + g    ][k0 + tig + 4]);
            uint32_t a3 = __float_as_uint(sP[warpM + g + 8][k0 + tig + 4]);
            #pragma unroll
            for (int nt = 0; nt < 8; nt++) {
                uint32_t b0 = __float_as_uint(sV[k0 + tig    ][nt * 8 + g]);
                uint32_t b1 = __float_as_uint(sV[k0 + tig + 4][nt * 8 + g]);
                mma_tf32(o[nt], a0, a1, a2, a3, b0, b1);
            }
        }
    }

    // ---- finalize ----
    const float inv0 = 1.0f / l0, inv1 = 1.0f / l1;
    #pragma unroll
    for (int nt = 0; nt < 8; nt++) {
        const int col = nt * 8 + 2 * tig;
        *reinterpret_cast<float2*>(
            &g_O[base + (size_t)(q0 + warpM + g) * DMODEL + col]) =
            make_float2(o[nt][0] * inv0, o[nt][1] * inv0);
        *reinterpret_cast<float2*>(
            &g_O[base + (size_t)(q0 + warpM + g + 8) * DMODEL + col]) =
            make_float2(o[nt][2] * inv1, o[nt][3] * inv1);
    }
}

// ---------------------------------------------------------------------------
// Projection: out = g_O @ W^T + bias, tf32 MMA.
// 128x128 block tile, BK=32, 8 warps in 2(m) x 4(n), warp tile 64x32.
// ---------------------------------------------------------------------------
__global__ __launch_bounds__(256)
void proj_kernel(const float* __restrict__ W,
                 const float* __restrict__ bias,
                 float* __restrict__ out)
{
    __shared__ float sA[128][36];   // 18 KB
    __shared__ float sB[128][36];   // 18 KB

    const int t    = threadIdx.x;
    const int lane = t & 31;
    const int wid  = t >> 5;
    const int g    = lane >> 2;
    const int tig  = lane & 3;
    const int wm   = (wid >> 2) * 64;   // warp m origin
    const int wn   = (wid & 3) * 32;    // warp n origin
    const int m0   = blockIdx.y * 128;
    const int n0   = blockIdx.x * 128;

    float acc[4][4][4] = {};            // [mtile][ntile][reg]

    const int r = t >> 1, half = t & 1;

    for (int k0 = 0; k0 < DMODEL; k0 += 32) {
        __syncthreads();
        {
            const float* ap = g_O + (size_t)(m0 + r) * DMODEL + k0 + half * 16;
            const float* wp = W   + (size_t)(n0 + r) * DMODEL + k0 + half * 16;
            #pragma unroll
            for (int u = 0; u < 4; u++) {
                float4 av = *reinterpret_cast<const float4*>(ap + u * 4);
                const int d = half * 16 + u * 4;
                CVT4(sA, r, d, av);
                float4 wv = *reinterpret_cast<const float4*>(wp + u * 4);
                CVT4(sB, r, d, wv);
            }
        }
        __syncthreads();

        #pragma unroll
        for (int kk = 0; kk < 32; kk += 8) {
            uint32_t a[4][4];
            #pragma unroll
            for (int mt = 0; mt < 4; mt++) {
                a[mt][0] = __float_as_uint(sA[wm + mt * 16 + g    ][kk + tig    ]);
                a[mt][1] = __float_as_uint(sA[wm + mt * 16 + g + 8][kk + tig    ]);
                a[mt][2] = __float_as_uint(sA[wm + mt * 16 + g    ][kk + tig + 4]);
                a[mt][3] = __float_as_uint(sA[wm + mt * 16 + g + 8][kk + tig + 4]);
            }
            #pragma unroll
            for (int nt = 0; nt < 4; nt++) {
                uint32_t b0 = __float_as_uint(sB[wn + nt * 8 + g][kk + tig    ]);
                uint32_t b1 = __float_as_uint(sB[wn + nt * 8 + g][kk + tig + 4]);
                #pragma unroll
                for (int mt = 0; mt < 4; mt++)
                    mma_tf32(acc[mt][nt], a[mt][0], a[mt][1], a[mt][2], a[mt][3], b0, b1);
            }
        }
    }

    // ---- epilogue with bias ----
    #pragma unroll
    for (int mt = 0; mt < 4; mt++) {
        const int row = m0 + wm + mt * 16 + g;
        #pragma unroll
        for (int nt = 0; nt < 4; nt++) {
            const int col = n0 + wn + nt * 8 + 2 * tig;
            const float b0v = bias[col], b1v = bias[col + 1];
            *reinterpret_cast<float2*>(out + (size_t)row * DMODEL + col) =
                make_float2(acc[mt][nt][0] + b0v, acc[mt][nt][1] + b1v);
            *reinterpret_cast<float2*>(out + (size_t)(row + 8) * DMODEL + col) =
                make_float2(acc[mt][nt][2] + b0v, acc[mt][nt][3] + b1v);
        }
    }
}

// ---------------------------------------------------------------------------
extern "C" void kernel_launch(void* const* d_in, const int* in_sizes, int n_in,
                              void* d_out, int out_size)
{
    const float* Q  = (const float*)d_in[0];
    const float* K  = (const float*)d_in[1];
    const float* V  = (const float*)d_in[2];
    const float* W  = (const float*)d_in[3];
    const float* bi = (const float*)d_in[4];
    float* out = (float*)d_out;

    dim3 agrid(LEN / TQ, HEADS, BATCH);
    attn_kernel<<<agrid, 128>>>(Q, K, V);

    dim3 pgrid(DMODEL / 128, (BATCH * LEN) / 128);
    proj_kernel<<<pgrid, 256>>>(W, bi, out);
}

// round 4
// speedup vs baseline: 16.6572x; 1.0815x over previous
#include <cuda_runtime.h>
#include <cuda_bf16.h>
#include <math_constants.h>
#include <cstdint>

// Problem constants
#define BATCH  4
#define LEN    1024
#define DMODEL 1024
#define HEADS  16
#define HDIM   64
// scale * log2(e):  (1/32) * 1.4426950408889634
#define SL2E   0.04508422002778011f

// Attention tiling: 64 q-rows per block, K/V tile = 32, 4 warps, double-buffered
#define TQ 64
#define TK 32
#define NT (LEN / TK)

// Projection: 128x128 tile, BK=32, 8 warps (2x4), warp tile 64x32, double-buffered
#define PBK 32
#define PROJ_SMEM (2 * 2 * 128 * 36 * 4)

// Scratch for attention output (device global; allocs forbidden)
__device__ float g_O[BATCH * LEN * DMODEL];

// ---- helpers -------------------------------------------------------------

__device__ __forceinline__ float tf32f(float x) {
    uint32_t u;
    asm("cvt.rna.tf32.f32 %0, %1;" : "=r"(u) : "f"(x));
    return __uint_as_float(u);
}
__device__ __forceinline__ float ex2f(float x) {
    float y;
    asm("ex2.approx.ftz.f32 %0, %1;" : "=f"(y) : "f"(x));
    return y;
}

// D = A(16x8,row) * B(8x8,col) + D, tf32 inputs, f32 accum
__device__ __forceinline__ void mma_tf32(float c[4],
                                         uint32_t a0, uint32_t a1, uint32_t a2, uint32_t a3,
                                         uint32_t b0, uint32_t b1) {
    asm volatile(
        "mma.sync.aligned.m16n8k8.row.col.f32.tf32.tf32.f32 "
        "{%0,%1,%2,%3}, {%4,%5,%6,%7}, {%8,%9}, {%0,%1,%2,%3};"
        : "+f"(c[0]), "+f"(c[1]), "+f"(c[2]), "+f"(c[3])
        : "r"(a0), "r"(a1), "r"(a2), "r"(a3), "r"(b0), "r"(b1));
}

#define CVT4(dst, v4)                  \
    dst[0] = tf32f(v4.x);              \
    dst[1] = tf32f(v4.y);              \
    dst[2] = tf32f(v4.z);              \
    dst[3] = tf32f(v4.w);

// ---------------------------------------------------------------------------
// Flash-style attention, tf32 MMA, Q in registers, max-free streaming softmax,
// double-buffered K/V tiles. Block = (b,h,64 q rows), 128 threads (4 warps).
// ---------------------------------------------------------------------------
__global__ __launch_bounds__(128)
void attn_kernel(const float* __restrict__ Q,
                 const float* __restrict__ K,
                 const float* __restrict__ V)
{
    __shared__ float sK[2][TK][68];   // 17.0 KB (also reused as Q staging temp)
    __shared__ float sV[2][TK][72];   // 18.0 KB
    __shared__ float sP[TQ][36];      //  9.0 KB

    const int t    = threadIdx.x;
    const int lane = t & 31;
    const int wid  = t >> 5;
    const int g    = lane >> 2;
    const int tig  = lane & 3;
    const int warpM = wid * 16;

    const int b  = blockIdx.z;
    const int h  = blockIdx.y;
    const int q0 = blockIdx.x * TQ;
    const size_t base = (size_t)b * LEN * DMODEL + (size_t)h * HDIM;

    // ---- stage Q into temp smem (alias of sK), then lift fragments to regs ----
    float (*tmpQ)[68] = reinterpret_cast<float(*)[68]>(&sK[0][0][0]);  // [64][68]
    {
        const int r = t >> 1, half = t & 1;
        const float* qp = Q + base + (size_t)(q0 + r) * DMODEL + half * 32;
        #pragma unroll
        for (int u = 0; u < 8; u++) {
            float4 v4 = *reinterpret_cast<const float4*>(qp + u * 4);
            CVT4((&tmpQ[r][half * 32 + u * 4]), v4);
        }
    }
    __syncthreads();

    uint32_t qf[8][4];
    #pragma unroll
    for (int ks = 0; ks < 8; ks++) {
        qf[ks][0] = __float_as_uint(tmpQ[warpM + g    ][ks * 8 + tig    ]);
        qf[ks][1] = __float_as_uint(tmpQ[warpM + g + 8][ks * 8 + tig    ]);
        qf[ks][2] = __float_as_uint(tmpQ[warpM + g    ][ks * 8 + tig + 4]);
        qf[ks][3] = __float_as_uint(tmpQ[warpM + g + 8][ks * 8 + tig + 4]);
    }
    __syncthreads();

    float o[8][4] = {};
    float lsum0 = 0.f, lsum1 = 0.f;

    const int kr = t >> 2;   // 0..31 (K/V tile row)
    const int kq = t & 3;    // 0..3  (16-float column chunk)

    // stage K/V tile kt into buffer buf
    auto stage = [&](int buf, int kt) {
        const float* kp = K + base + (size_t)(kt * TK + kr) * DMODEL + kq * 16;
        const float* vp = V + base + (size_t)(kt * TK + kr) * DMODEL + kq * 16;
        #pragma unroll
        for (int u = 0; u < 4; u++) {
            float4 kv = *reinterpret_cast<const float4*>(kp + u * 4);
            CVT4((&sK[buf][kr][kq * 16 + u * 4]), kv);
            float4 vv = *reinterpret_cast<const float4*>(vp + u * 4);
            CVT4((&sV[buf][kr][kq * 16 + u * 4]), vv);
        }
    };

    stage(0, 0);
    __syncthreads();

    for (int kt = 0; kt < NT; kt++) {
        const int buf = kt & 1;
        if (kt + 1 < NT) stage(buf ^ 1, kt + 1);   // LDGs overlap compute below

        // ---- S = Q K^T : 4 ntiles x 8 k-steps ----
        float s[4][4] = {};
        #pragma unroll
        for (int ks = 0; ks < 8; ks++) {
            #pragma unroll
            for (int nt = 0; nt < 4; nt++) {
                uint32_t b0 = __float_as_uint(sK[buf][nt * 8 + g][ks * 8 + tig    ]);
                uint32_t b1 = __float_as_uint(sK[buf][nt * 8 + g][ks * 8 + tig + 4]);
                mma_tf32(s[nt], qf[ks][0], qf[ks][1], qf[ks][2], qf[ks][3], b0, b1);
            }
        }

        // ---- max-free softmax: p = 2^(s*SL2E) ----
        #pragma unroll
        for (int nt = 0; nt < 4; nt++) {
            float p00 = ex2f(s[nt][0] * SL2E);
            float p01 = ex2f(s[nt][1] * SL2E);
            float p10 = ex2f(s[nt][2] * SL2E);
            float p11 = ex2f(s[nt][3] * SL2E);
            lsum0 += p00 + p01;
            lsum1 += p10 + p11;
            *reinterpret_cast<float2*>(&sP[warpM + g    ][nt * 8 + 2 * tig]) =
                make_float2(tf32f(p00), tf32f(p01));
            *reinterpret_cast<float2*>(&sP[warpM + g + 8][nt * 8 + 2 * tig]) =
                make_float2(tf32f(p10), tf32f(p11));
        }
        __syncwarp();

        // ---- O += P V : 8 d-ntiles x 4 k-steps ----
        #pragma unroll
        for (int k0 = 0; k0 < TK; k0 += 8) {
            uint32_t a0 = __float_as_uint(sP[warpM + g    ][k0 + tig    ]);
            uint32_t a1 = __float_as_uint(sP[warpM + g + 8][k0 + tig    ]);
            uint32_t a2 = __float_as_uint(sP[warpM + g    ][k0 + tig + 4]);
            uint32_t a3 = __float_as_uint(sP[warpM + g + 8][k0 + tig + 4]);
            #pragma unroll
            for (int nt = 0; nt < 8; nt++) {
                uint32_t b0 = __float_as_uint(sV[buf][k0 + tig    ][nt * 8 + g]);
                uint32_t b1 = __float_as_uint(sV[buf][k0 + tig + 4][nt * 8 + g]);
                mma_tf32(o[nt], a0, a1, a2, a3, b0, b1);
            }
        }
        __syncthreads();   // buf fully consumed; buf^1 stores visible
    }

    // ---- final row-sum reduce (lanes sharing g: xor 1, 2) ----
    lsum0 += __shfl_xor_sync(0xffffffffu, lsum0, 1);
    lsum0 += __shfl_xor_sync(0xffffffffu, lsum0, 2);
    lsum1 += __shfl_xor_sync(0xffffffffu, lsum1, 1);
    lsum1 += __shfl_xor_sync(0xffffffffu, lsum1, 2);
    const float inv0 = 1.0f / lsum0, inv1 = 1.0f / lsum1;

    #pragma unroll
    for (int nt = 0; nt < 8; nt++) {
        const int col = nt * 8 + 2 * tig;
        *reinterpret_cast<float2*>(
            &g_O[base + (size_t)(q0 + warpM + g) * DMODEL + col]) =
            make_float2(o[nt][0] * inv0, o[nt][1] * inv0);
        *reinterpret_cast<float2*>(
            &g_O[base + (size_t)(q0 + warpM + g + 8) * DMODEL + col]) =
            make_float2(o[nt][2] * inv1, o[nt][3] * inv1);
    }
}

// ---------------------------------------------------------------------------
// Projection: out = g_O @ W^T + bias, tf32 MMA, double-buffered tiles.
// 128x128 tile, BK=32, 8 warps (2m x 4n), warp tile 64x32.
// ---------------------------------------------------------------------------
extern __shared__ float dsm[];

__global__ __launch_bounds__(256)
void proj_kernel(const float* __restrict__ W,
                 const float* __restrict__ bias,
                 float* __restrict__ out)
{
    float (*sA)[128][36] = reinterpret_cast<float(*)[128][36]>(dsm);
    float (*sB)[128][36] = reinterpret_cast<float(*)[128][36]>(dsm + 2 * 128 * 36);

    const int t    = threadIdx.x;
    const int lane = t & 31;
    const int wid  = t >> 5;
    const int g    = lane >> 2;
    const int tig  = lane & 3;
    const int wm   = (wid >> 2) * 64;
    const int wn   = (wid & 3) * 32;
    const int m0   = blockIdx.y * 128;
    const int n0   = blockIdx.x * 128;

    const int r = t >> 1, half = t & 1;

    auto stage = [&](int buf, int k0) {
        const float* ap = g_O + (size_t)(m0 + r) * DMODEL + k0 + half * 16;
        const float* wp = W   + (size_t)(n0 + r) * DMODEL + k0 + half * 16;
        #pragma unroll
        for (int u = 0; u < 4; u++) {
            float4 av = *reinterpret_cast<const float4*>(ap + u * 4);
            CVT4((&sA[buf][r][half * 16 + u * 4]), av);
            float4 wv = *reinterpret_cast<const float4*>(wp + u * 4);
            CVT4((&sB[buf][r][half * 16 + u * 4]), wv);
        }
    };

    float acc[4][4][4] = {};

    stage(0, 0);
    __syncthreads();

    const int NITER = DMODEL / PBK;   // 32
    for (int i = 0; i < NITER; i++) {
        const int buf = i & 1;
        if (i + 1 < NITER) stage(buf ^ 1, (i + 1) * PBK);

        #pragma unroll
        for (int kk = 0; kk < PBK; kk += 8) {
            uint32_t a[4][4];
            #pragma unroll
            for (int mt = 0; mt < 4; mt++) {
                a[mt][0] = __float_as_uint(sA[buf][wm + mt * 16 + g    ][kk + tig    ]);
                a[mt][1] = __float_as_uint(sA[buf][wm + mt * 16 + g + 8][kk + tig    ]);
                a[mt][2] = __float_as_uint(sA[buf][wm + mt * 16 + g    ][kk + tig + 4]);
                a[mt][3] = __float_as_uint(sA[buf][wm + mt * 16 + g + 8][kk + tig + 4]);
            }
            #pragma unroll
            for (int nt = 0; nt < 4; nt++) {
                uint32_t b0 = __float_as_uint(sB[buf][wn + nt * 8 + g][kk + tig    ]);
                uint32_t b1 = __float_as_uint(sB[buf][wn + nt * 8 + g][kk + tig + 4]);
                #pragma unroll
                for (int mt = 0; mt < 4; mt++)
                    mma_tf32(acc[mt][nt], a[mt][0], a[mt][1], a[mt][2], a[mt][3], b0, b1);
            }
        }
        __syncthreads();
    }

    // ---- epilogue with bias ----
    #pragma unroll
    for (int mt = 0; mt < 4; mt++) {
        const int row = m0 + wm + mt * 16 + g;
        #pragma unroll
        for (int nt = 0; nt < 4; nt++) {
            const int col = n0 + wn + nt * 8 + 2 * tig;
            const float b0v = bias[col], b1v = bias[col + 1];
            *reinterpret_cast<float2*>(out + (size_t)row * DMODEL + col) =
                make_float2(acc[mt][nt][0] + b0v, acc[mt][nt][1] + b1v);
            *reinterpret_cast<float2*>(out + (size_t)(row + 8) * DMODEL + col) =
                make_float2(acc[mt][nt][2] + b0v, acc[mt][nt][3] + b1v);
        }
    }
}

// ---------------------------------------------------------------------------
extern "C" void kernel_launch(void* const* d_in, const int* in_sizes, int n_in,
                              void* d_out, int out_size)
{
    const float* Q  = (const float*)d_in[0];
    const float* K  = (const float*)d_in[1];
    const float* V  = (const float*)d_in[2];
    const float* W  = (const float*)d_in[3];
    const float* bi = (const float*)d_in[4];
    float* out = (float*)d_out;

    cudaFuncSetAttribute(proj_kernel,
                         cudaFuncAttributeMaxDynamicSharedMemorySize, PROJ_SMEM);

    dim3 agrid(LEN / TQ, HEADS, BATCH);
    attn_kernel<<<agrid, 128>>>(Q, K, V);

    dim3 pgrid(DMODEL / 128, (BATCH * LEN) / 128);
    proj_kernel<<<pgrid, 256, PROJ_SMEM>>>(W, bi, out);
}

// round 5
// speedup vs baseline: 17.2056x; 1.0329x over previous
#include <cuda_runtime.h>
#include <cuda_bf16.h>
#include <math_constants.h>
#include <cstdint>

// Problem constants
#define BATCH  4
#define LEN    1024
#define DMODEL 1024
#define HEADS  16
#define HDIM   64
// scale * log2(e):  (1/32) * 1.4426950408889634
#define SL2E   0.04508422002778011f

// Attention tiling: 64 q-rows per block, K/V tile = 32, 4 warps, double-buffered
#define TQ 64
#define TK 32
#define NT (LEN / TK)

// Projection: 128x128 tile, BK=32, 8 warps (2x4), warp tile 64x32, double-buffered
#define PBK 32
#define PROJ_SMEM (2 * 2 * 128 * 36 * 4)

// Scratch for attention output (device global; allocs forbidden)
__device__ float g_O[BATCH * LEN * DMODEL];

// ---- helpers -------------------------------------------------------------

__device__ __forceinline__ float tf32f(float x) {
    uint32_t u;
    asm("cvt.rna.tf32.f32 %0, %1;" : "=r"(u) : "f"(x));
    return __uint_as_float(u);
}
__device__ __forceinline__ float ex2f(float x) {
    float y;
    asm("ex2.approx.ftz.f32 %0, %1;" : "=f"(y) : "f"(x));
    return y;
}

// D = A(16x8,row) * B(8x8,col) + D, tf32 inputs, f32 accum
__device__ __forceinline__ void mma_tf32(float c[4],
                                         uint32_t a0, uint32_t a1, uint32_t a2, uint32_t a3,
                                         uint32_t b0, uint32_t b1) {
    asm volatile(
        "mma.sync.aligned.m16n8k8.row.col.f32.tf32.tf32.f32 "
        "{%0,%1,%2,%3}, {%4,%5,%6,%7}, {%8,%9}, {%0,%1,%2,%3};"
        : "+f"(c[0]), "+f"(c[1]), "+f"(c[2]), "+f"(c[3])
        : "r"(a0), "r"(a1), "r"(a2), "r"(a3), "r"(b0), "r"(b1));
}

// ldmatrix x4 (each 8x8 b16 matrix == 8x4 tf32; lane l <- (row l>>2, tf32col l&3))
__device__ __forceinline__ void ldsm_x4(uint32_t& r0, uint32_t& r1,
                                        uint32_t& r2, uint32_t& r3,
                                        const float* p) {
    uint32_t addr = (uint32_t)__cvta_generic_to_shared(p);
    asm volatile("ldmatrix.sync.aligned.m8n8.x4.shared.b16 {%0,%1,%2,%3}, [%4];"
                 : "=r"(r0), "=r"(r1), "=r"(r2), "=r"(r3) : "r"(addr));
}

#define CVT4(dst, v4)                  \
    dst[0] = tf32f(v4.x);              \
    dst[1] = tf32f(v4.y);              \
    dst[2] = tf32f(v4.z);              \
    dst[3] = tf32f(v4.w);

// ---------------------------------------------------------------------------
// Flash-style attention, tf32 MMA, Q in registers, max-free streaming softmax,
// double-buffered K/V tiles, ldmatrix fragment loads.
// Block = (b,h,64 q rows), 128 threads (4 warps).
// ---------------------------------------------------------------------------
__global__ __launch_bounds__(128)
void attn_kernel(const float* __restrict__ Q,
                 const float* __restrict__ K,
                 const float* __restrict__ V)
{
    __shared__ alignas(16) float sK[2][TK][68];   // 17.0 KB (reused as Q staging)
    __shared__ alignas(16) float sV[2][TK][72];   // 18.0 KB
    __shared__ alignas(16) float sP[TQ][36];      //  9.0 KB

    const int t    = threadIdx.x;
    const int lane = t & 31;
    const int wid  = t >> 5;
    const int g    = lane >> 2;
    const int tig  = lane & 3;
    const int warpM = wid * 16;

    const int b  = blockIdx.z;
    const int h  = blockIdx.y;
    const int q0 = blockIdx.x * TQ;
    const size_t base = (size_t)b * LEN * DMODEL + (size_t)h * HDIM;

    // ldmatrix per-lane address components
    // K (B-frag pair): mats [(ntp+hi)*8 + r][ks*8 + lo*4], hi=(l>>4)&1, lo=(l>>3)&1
    const int kRow = ((lane >> 4) & 1) * 8 + (lane & 7);
    const int kCol = ((lane >> 3) & 1) * 4;
    // P (A-frag): mats [warpM + hi*8 + r][k0 + lo*4], hi=(l>>3)&1, lo=(l>>4)&1
    const int pRow = warpM + ((lane >> 3) & 1) * 8 + (lane & 7);
    const int pCol = ((lane >> 4) & 1) * 4;

    // ---- stage Q into temp smem (alias of sK), lift fragments to registers ----
    float (*tmpQ)[68] = reinterpret_cast<float(*)[68]>(&sK[0][0][0]);  // [64][68]
    {
        const int r = t >> 1, half = t & 1;
        const float* qp = Q + base + (size_t)(q0 + r) * DMODEL + half * 32;
        #pragma unroll
        for (int u = 0; u < 8; u++) {
            float4 v4 = *reinterpret_cast<const float4*>(qp + u * 4);
            CVT4((&tmpQ[r][half * 32 + u * 4]), v4);
        }
    }
    __syncthreads();

    uint32_t qf[8][4];
    #pragma unroll
    for (int ks = 0; ks < 8; ks++)
        ldsm_x4(qf[ks][0], qf[ks][1], qf[ks][2], qf[ks][3],
                &tmpQ[pRow][ks * 8 + pCol]);
    __syncthreads();

    float o[8][4] = {};
    float lsum0 = 0.f, lsum1 = 0.f;

    const int kr = t >> 2;   // 0..31 (K/V tile row)
    const int kq = t & 3;    // 0..3

    auto stage = [&](int buf, int kt) {
        const float* kp = K + base + (size_t)(kt * TK + kr) * DMODEL + kq * 16;
        const float* vp = V + base + (size_t)(kt * TK + kr) * DMODEL + kq * 16;
        #pragma unroll
        for (int u = 0; u < 4; u++) {
            float4 kv = *reinterpret_cast<const float4*>(kp + u * 4);
            CVT4((&sK[buf][kr][kq * 16 + u * 4]), kv);
            float4 vv = *reinterpret_cast<const float4*>(vp + u * 4);
            CVT4((&sV[buf][kr][kq * 16 + u * 4]), vv);
        }
    };

    stage(0, 0);
    __syncthreads();

    for (int kt = 0; kt < NT; kt++) {
        const int buf = kt & 1;
        if (kt + 1 < NT) stage(buf ^ 1, kt + 1);   // LDGs overlap compute

        // ---- S = Q K^T : 4 ntiles x 8 k-steps, B-frags via ldmatrix pairs ----
        float s[4][4] = {};
        #pragma unroll
        for (int ks = 0; ks < 8; ks++) {
            uint32_t b00, b01, b10, b11;
            ldsm_x4(b00, b01, b10, b11, &sK[buf][kRow][ks * 8 + kCol]);       // nt 0,1
            mma_tf32(s[0], qf[ks][0], qf[ks][1], qf[ks][2], qf[ks][3], b00, b01);
            mma_tf32(s[1], qf[ks][0], qf[ks][1], qf[ks][2], qf[ks][3], b10, b11);
            uint32_t b20, b21, b30, b31;
            ldsm_x4(b20, b21, b30, b31, &sK[buf][16 + kRow][ks * 8 + kCol]);  // nt 2,3
            mma_tf32(s[2], qf[ks][0], qf[ks][1], qf[ks][2], qf[ks][3], b20, b21);
            mma_tf32(s[3], qf[ks][0], qf[ks][1], qf[ks][2], qf[ks][3], b30, b31);
        }

        // ---- max-free softmax: p = 2^(s*SL2E) ----
        #pragma unroll
        for (int nt = 0; nt < 4; nt++) {
            float p00 = ex2f(s[nt][0] * SL2E);
            float p01 = ex2f(s[nt][1] * SL2E);
            float p10 = ex2f(s[nt][2] * SL2E);
            float p11 = ex2f(s[nt][3] * SL2E);
            lsum0 += p00 + p01;
            lsum1 += p10 + p11;
            *reinterpret_cast<float2*>(&sP[warpM + g    ][nt * 8 + 2 * tig]) =
                make_float2(tf32f(p00), tf32f(p01));
            *reinterpret_cast<float2*>(&sP[warpM + g + 8][nt * 8 + 2 * tig]) =
                make_float2(tf32f(p10), tf32f(p11));
        }
        __syncwarp();

        // ---- O += P V : A-frags via ldmatrix, V B-frags scalar (conflict-free) ----
        #pragma unroll
        for (int k0 = 0; k0 < TK; k0 += 8) {
            uint32_t a0, a1, a2, a3;
            ldsm_x4(a0, a1, a2, a3, &sP[pRow][k0 + pCol]);
            #pragma unroll
            for (int nt = 0; nt < 8; nt++) {
                uint32_t b0 = __float_as_uint(sV[buf][k0 + tig    ][nt * 8 + g]);
                uint32_t b1 = __float_as_uint(sV[buf][k0 + tig + 4][nt * 8 + g]);
                mma_tf32(o[nt], a0, a1, a2, a3, b0, b1);
            }
        }
        __syncthreads();
    }

    // ---- final row-sum reduce (lanes sharing g: xor 1, 2) ----
    lsum0 += __shfl_xor_sync(0xffffffffu, lsum0, 1);
    lsum0 += __shfl_xor_sync(0xffffffffu, lsum0, 2);
    lsum1 += __shfl_xor_sync(0xffffffffu, lsum1, 1);
    lsum1 += __shfl_xor_sync(0xffffffffu, lsum1, 2);
    const float inv0 = 1.0f / lsum0, inv1 = 1.0f / lsum1;

    #pragma unroll
    for (int nt = 0; nt < 8; nt++) {
        const int col = nt * 8 + 2 * tig;
        *reinterpret_cast<float2*>(
            &g_O[base + (size_t)(q0 + warpM + g) * DMODEL + col]) =
            make_float2(o[nt][0] * inv0, o[nt][1] * inv0);
        *reinterpret_cast<float2*>(
            &g_O[base + (size_t)(q0 + warpM + g + 8) * DMODEL + col]) =
            make_float2(o[nt][2] * inv1, o[nt][3] * inv1);
    }
}

// ---------------------------------------------------------------------------
// Projection: out = g_O @ W^T + bias, tf32 MMA, double-buffered, ldmatrix frags.
// 128x128 tile, BK=32, 8 warps (2m x 4n), warp tile 64x32.
// ---------------------------------------------------------------------------
extern __shared__ float dsm[];

__global__ __launch_bounds__(256)
void proj_kernel(const float* __restrict__ W,
                 const float* __restrict__ bias,
                 float* __restrict__ out)
{
    float (*sA)[128][36] = reinterpret_cast<float(*)[128][36]>(dsm);
    float (*sB)[128][36] = reinterpret_cast<float(*)[128][36]>(dsm + 2 * 128 * 36);

    const int t    = threadIdx.x;
    const int lane = t & 31;
    const int wid  = t >> 5;
    const int g    = lane >> 2;
    const int tig  = lane & 3;
    const int wm   = (wid >> 2) * 64;
    const int wn   = (wid & 3) * 32;
    const int m0   = blockIdx.y * 128;
    const int n0   = blockIdx.x * 128;

    // ldmatrix lane address components
    const int aRow = ((lane >> 3) & 1) * 8 + (lane & 7);  // A-frag (row-block bit)
    const int aCol = ((lane >> 4) & 1) * 4;
    const int bRow = ((lane >> 4) & 1) * 8 + (lane & 7);  // B-frag pair (nt bit)
    const int bCol = ((lane >> 3) & 1) * 4;

    const int r = t >> 1, half = t & 1;

    auto stage = [&](int buf, int k0) {
        const float* ap = g_O + (size_t)(m0 + r) * DMODEL + k0 + half * 16;
        const float* wp = W   + (size_t)(n0 + r) * DMODEL + k0 + half * 16;
        #pragma unroll
        for (int u = 0; u < 4; u++) {
            float4 av = *reinterpret_cast<const float4*>(ap + u * 4);
            CVT4((&sA[buf][r][half * 16 + u * 4]), av);
            float4 wv = *reinterpret_cast<const float4*>(wp + u * 4);
            CVT4((&sB[buf][r][half * 16 + u * 4]), wv);
        }
    };

    float acc[4][4][4] = {};

    stage(0, 0);
    __syncthreads();

    const int NITER = DMODEL / PBK;   // 32
    for (int i = 0; i < NITER; i++) {
        const int buf = i & 1;
        if (i + 1 < NITER) stage(buf ^ 1, (i + 1) * PBK);

        #pragma unroll
        for (int kk = 0; kk < PBK; kk += 8) {
            uint32_t a[4][4];
            #pragma unroll
            for (int mt = 0; mt < 4; mt++)
                ldsm_x4(a[mt][0], a[mt][1], a[mt][2], a[mt][3],
                        &sA[buf][wm + mt * 16 + aRow][kk + aCol]);

            uint32_t bf[4][2];
            ldsm_x4(bf[0][0], bf[0][1], bf[1][0], bf[1][1],
                    &sB[buf][wn + bRow][kk + bCol]);          // nt 0,1
            ldsm_x4(bf[2][0], bf[2][1], bf[3][0], bf[3][1],
                    &sB[buf][wn + 16 + bRow][kk + bCol]);     // nt 2,3

            #pragma unroll
            for (int nt = 0; nt < 4; nt++)
                #pragma unroll
                for (int mt = 0; mt < 4; mt++)
                    mma_tf32(acc[mt][nt], a[mt][0], a[mt][1], a[mt][2], a[mt][3],
                             bf[nt][0], bf[nt][1]);
        }
        __syncthreads();
    }

    // ---- epilogue with bias ----
    #pragma unroll
    for (int mt = 0; mt < 4; mt++) {
        const int row = m0 + wm + mt * 16 + g;
        #pragma unroll
        for (int nt = 0; nt < 4; nt++) {
            const int col = n0 + wn + nt * 8 + 2 * tig;
            const float b0v = bias[col], b1v = bias[col + 1];
            *reinterpret_cast<float2*>(out + (size_t)row * DMODEL + col) =
                make_float2(acc[mt][nt][0] + b0v, acc[mt][nt][1] + b1v);
            *reinterpret_cast<float2*>(out + (size_t)(row + 8) * DMODEL + col) =
                make_float2(acc[mt][nt][2] + b0v, acc[mt][nt][3] + b1v);
        }
    }
}

// ---------------------------------------------------------------------------
extern "C" void kernel_launch(void* const* d_in, const int* in_sizes, int n_in,
                              void* d_out, int out_size)
{
    const float* Q  = (const float*)d_in[0];
    const float* K  = (const float*)d_in[1];
    const float* V  = (const float*)d_in[2];
    const float* W  = (const float*)d_in[3];
    const float* bi = (const float*)d_in[4];
    float* out = (float*)d_out;

    cudaFuncSetAttribute(proj_kernel,
                         cudaFuncAttributeMaxDynamicSharedMemorySize, PROJ_SMEM);

    dim3 agrid(LEN / TQ, HEADS, BATCH);
    attn_kernel<<<agrid, 128>>>(Q, K, V);

    dim3 pgrid(DMODEL / 128, (BATCH * LEN) / 128);
    proj_kernel<<<pgrid, 256, PROJ_SMEM>>>(W, bi, out);
}

// round 6
// speedup vs baseline: 22.2888x; 1.2954x over previous
#include <cuda_runtime.h>
#include <cuda_bf16.h>
#include <math_constants.h>
#include <cstdint>

// Problem constants
#define BATCH  4
#define LEN    1024
#define DMODEL 1024
#define HEADS  16
#define HDIM   64
// scale * log2(e):  (1/32) * 1.4426950408889634
#define SL2E   0.04508422002778011f

// Attention tiling: 128 q-rows per block, 4 warps x 32 rows, K/V tile 32, dbl-buffered
#define TQ 128
#define TK 32
#define NT (LEN / TK)
// smem (floats): sK 2*32*68=4352 | sV 2*32*72=4608 | sP 128*36=4608
#define ATTN_SK_OFF 0
#define ATTN_SV_OFF 4352
#define ATTN_SP_OFF 8960
#define ATTN_SMEM   (13568 * 4)

// Projection: 128x256 block tile, BK=32, 8 warps (2m x 4n), warp tile 64x64
#define PBK 32
#define PROJ_SB_OFF (2 * 128 * 36)
#define PROJ_SMEM   ((2 * 128 * 36 + 2 * 256 * 36) * 4)

__device__ float g_O[BATCH * LEN * DMODEL];

// ---- helpers -------------------------------------------------------------

__device__ __forceinline__ float tf32f(float x) {
    uint32_t u;
    asm("cvt.rna.tf32.f32 %0, %1;" : "=r"(u) : "f"(x));
    return __uint_as_float(u);
}
__device__ __forceinline__ float ex2f(float x) {
    float y;
    asm("ex2.approx.ftz.f32 %0, %1;" : "=f"(y) : "f"(x));
    return y;
}

__device__ __forceinline__ void mma_tf32(float c[4],
                                         uint32_t a0, uint32_t a1, uint32_t a2, uint32_t a3,
                                         uint32_t b0, uint32_t b1) {
    asm volatile(
        "mma.sync.aligned.m16n8k8.row.col.f32.tf32.tf32.f32 "
        "{%0,%1,%2,%3}, {%4,%5,%6,%7}, {%8,%9}, {%0,%1,%2,%3};"
        : "+f"(c[0]), "+f"(c[1]), "+f"(c[2]), "+f"(c[3])
        : "r"(a0), "r"(a1), "r"(a2), "r"(a3), "r"(b0), "r"(b1));
}

// ldmatrix x4 (each 8x8 b16 matrix == 8x4 tf32)
__device__ __forceinline__ void ldsm_x4(uint32_t& r0, uint32_t& r1,
                                        uint32_t& r2, uint32_t& r3,
                                        const float* p) {
    uint32_t addr = (uint32_t)__cvta_generic_to_shared(p);
    asm volatile("ldmatrix.sync.aligned.m8n8.x4.shared.b16 {%0,%1,%2,%3}, [%4];"
                 : "=r"(r0), "=r"(r1), "=r"(r2), "=r"(r3) : "r"(addr));
}

#define CVT4(dst, v4)                  \
    dst[0] = tf32f(v4.x);              \
    dst[1] = tf32f(v4.y);              \
    dst[2] = tf32f(v4.z);              \
    dst[3] = tf32f(v4.w);

extern __shared__ float dsm[];

// ---------------------------------------------------------------------------
// Flash-style attention, tf32 MMA. Block = (b,h,128 q rows), 4 warps x 32 rows.
// Q fragments register-resident; max-free streaming softmax; double-buffered K/V.
// ---------------------------------------------------------------------------
__global__ __launch_bounds__(128)
void attn_kernel(const float* __restrict__ Q,
                 const float* __restrict__ K,
                 const float* __restrict__ V)
{
    float (*sK)[TK][68] = reinterpret_cast<float(*)[TK][68]>(dsm + ATTN_SK_OFF);
    float (*sV)[TK][72] = reinterpret_cast<float(*)[TK][72]>(dsm + ATTN_SV_OFF);
    float (*sP)[36]     = reinterpret_cast<float(*)[36]>(dsm + ATTN_SP_OFF);

    const int t    = threadIdx.x;
    const int lane = t & 31;
    const int wid  = t >> 5;
    const int g    = lane >> 2;
    const int tig  = lane & 3;
    const int warpM = wid * 32;          // 32 q-rows per warp (2 mtiles)

    const int b  = blockIdx.z;
    const int h  = blockIdx.y;
    const int q0 = blockIdx.x * TQ;
    const size_t base = (size_t)b * LEN * DMODEL + (size_t)h * HDIM;

    // ldmatrix lane address components
    const int kRow = ((lane >> 4) & 1) * 8 + (lane & 7);   // B-frag pair (K)
    const int kCol = ((lane >> 3) & 1) * 4;
    const int pRow = ((lane >> 3) & 1) * 8 + (lane & 7);   // A-frag (Q / P)
    const int pCol = ((lane >> 4) & 1) * 4;

    // ---- stage Q into temp smem (alias of sK+sV region), lift to registers ----
    float (*tmpQ)[68] = reinterpret_cast<float(*)[68]>(dsm);   // [128][68]
    {
        const int c = (t & 15) * 4;
        #pragma unroll
        for (int p = 0; p < 16; p++) {
            const int r = p * 8 + (t >> 4);
            float4 v4 = *reinterpret_cast<const float4*>(
                Q + base + (size_t)(q0 + r) * DMODEL + c);
            CVT4((&tmpQ[r][c]), v4);
        }
    }
    __syncthreads();

    uint32_t qf[2][8][4];
    #pragma unroll
    for (int mt = 0; mt < 2; mt++)
        #pragma unroll
        for (int ks = 0; ks < 8; ks++)
            ldsm_x4(qf[mt][ks][0], qf[mt][ks][1], qf[mt][ks][2], qf[mt][ks][3],
                    &tmpQ[warpM + mt * 16 + pRow][ks * 8 + pCol]);
    __syncthreads();

    float o[2][8][4] = {};
    float ls[2][2] = {{0.f, 0.f}, {0.f, 0.f}};   // [mt][row g / g+8]

    // K/V staging: 16 threads/row, 4 passes over 32 rows, coalesced
    const int sc = (t & 15) * 4;
    auto stage = [&](int buf, int kt) {
        #pragma unroll
        for (int p = 0; p < 4; p++) {
            const int r = p * 8 + (t >> 4);
            const size_t go = base + (size_t)(kt * TK + r) * DMODEL + sc;
            float4 kv = *reinterpret_cast<const float4*>(K + go);
            CVT4((&sK[buf][r][sc]), kv);
            float4 vv = *reinterpret_cast<const float4*>(V + go);
            CVT4((&sV[buf][r][sc]), vv);
        }
    };

    stage(0, 0);
    __syncthreads();

    for (int kt = 0; kt < NT; kt++) {
        const int buf = kt & 1;
        if (kt + 1 < NT) stage(buf ^ 1, kt + 1);

        // ---- S = Q K^T : 2 mtiles x 4 ntiles x 8 ks ----
        float s[2][4][4] = {};
        #pragma unroll
        for (int ks = 0; ks < 8; ks++) {
            uint32_t b00, b01, b10, b11;
            ldsm_x4(b00, b01, b10, b11, &sK[buf][kRow][ks * 8 + kCol]);
            uint32_t b20, b21, b30, b31;
            ldsm_x4(b20, b21, b30, b31, &sK[buf][16 + kRow][ks * 8 + kCol]);
            #pragma unroll
            for (int mt = 0; mt < 2; mt++) {
                mma_tf32(s[mt][0], qf[mt][ks][0], qf[mt][ks][1], qf[mt][ks][2], qf[mt][ks][3], b00, b01);
                mma_tf32(s[mt][1], qf[mt][ks][0], qf[mt][ks][1], qf[mt][ks][2], qf[mt][ks][3], b10, b11);
                mma_tf32(s[mt][2], qf[mt][ks][0], qf[mt][ks][1], qf[mt][ks][2], qf[mt][ks][3], b20, b21);
                mma_tf32(s[mt][3], qf[mt][ks][0], qf[mt][ks][1], qf[mt][ks][2], qf[mt][ks][3], b30, b31);
            }
        }

        // ---- max-free softmax: p = 2^(s*SL2E) ----
        #pragma unroll
        for (int mt = 0; mt < 2; mt++)
            #pragma unroll
            for (int nt = 0; nt < 4; nt++) {
                float p00 = ex2f(s[mt][nt][0] * SL2E);
                float p01 = ex2f(s[mt][nt][1] * SL2E);
                float p10 = ex2f(s[mt][nt][2] * SL2E);
                float p11 = ex2f(s[mt][nt][3] * SL2E);
                ls[mt][0] += p00 + p01;
                ls[mt][1] += p10 + p11;
                *reinterpret_cast<float2*>(&sP[warpM + mt * 16 + g    ][nt * 8 + 2 * tig]) =
                    make_float2(tf32f(p00), tf32f(p01));
                *reinterpret_cast<float2*>(&sP[warpM + mt * 16 + g + 8][nt * 8 + 2 * tig]) =
                    make_float2(tf32f(p10), tf32f(p11));
            }
        __syncwarp();

        // ---- O += P V : per k0: 2 A-LDSM + 16 V LDS -> 16 MMAs ----
        #pragma unroll
        for (int k0 = 0; k0 < TK; k0 += 8) {
            uint32_t a[2][4];
            #pragma unroll
            for (int mt = 0; mt < 2; mt++)
                ldsm_x4(a[mt][0], a[mt][1], a[mt][2], a[mt][3],
                        &sP[warpM + mt * 16 + pRow][k0 + pCol]);
            #pragma unroll
            for (int nt = 0; nt < 8; nt++) {
                uint32_t b0 = __float_as_uint(sV[buf][k0 + tig    ][nt * 8 + g]);
                uint32_t b1 = __float_as_uint(sV[buf][k0 + tig + 4][nt * 8 + g]);
                mma_tf32(o[0][nt], a[0][0], a[0][1], a[0][2], a[0][3], b0, b1);
                mma_tf32(o[1][nt], a[1][0], a[1][1], a[1][2], a[1][3], b0, b1);
            }
        }
        __syncthreads();
    }

    // ---- final row-sum reduce across tig (xor 1,2), then write ----
    #pragma unroll
    for (int mt = 0; mt < 2; mt++) {
        ls[mt][0] += __shfl_xor_sync(0xffffffffu, ls[mt][0], 1);
        ls[mt][0] += __shfl_xor_sync(0xffffffffu, ls[mt][0], 2);
        ls[mt][1] += __shfl_xor_sync(0xffffffffu, ls[mt][1], 1);
        ls[mt][1] += __shfl_xor_sync(0xffffffffu, ls[mt][1], 2);
        const float inv0 = 1.0f / ls[mt][0], inv1 = 1.0f / ls[mt][1];
        #pragma unroll
        for (int nt = 0; nt < 8; nt++) {
            const int col = nt * 8 + 2 * tig;
            *reinterpret_cast<float2*>(
                &g_O[base + (size_t)(q0 + warpM + mt * 16 + g) * DMODEL + col]) =
                make_float2(o[mt][nt][0] * inv0, o[mt][nt][1] * inv0);
            *reinterpret_cast<float2*>(
                &g_O[base + (size_t)(q0 + warpM + mt * 16 + g + 8) * DMODEL + col]) =
                make_float2(o[mt][nt][2] * inv1, o[mt][nt][3] * inv1);
        }
    }
}

// ---------------------------------------------------------------------------
// Projection: out = g_O @ W^T + bias. 128x256 block tile, BK=32, 8 warps (2x4),
// warp tile 64x64, double-buffered, ldmatrix fragment loads.
// ---------------------------------------------------------------------------
__global__ __launch_bounds__(256)
void proj_kernel(const float* __restrict__ W,
                 const float* __restrict__ bias,
                 float* __restrict__ out)
{
    float (*sA)[128][36] = reinterpret_cast<float(*)[128][36]>(dsm);
    float (*sB)[256][36] = reinterpret_cast<float(*)[256][36]>(dsm + PROJ_SB_OFF);

    const int t    = threadIdx.x;
    const int lane = t & 31;
    const int wid  = t >> 5;
    const int g    = lane >> 2;
    const int tig  = lane & 3;
    const int wm   = (wid >> 2) * 64;   // 2 warp-rows
    const int wn   = (wid & 3) * 64;    // 4 warp-cols
    const int m0   = blockIdx.y * 128;
    const int n0   = blockIdx.x * 256;

    const int aRow = ((lane >> 3) & 1) * 8 + (lane & 7);
    const int aCol = ((lane >> 4) & 1) * 4;
    const int bRow = ((lane >> 4) & 1) * 8 + (lane & 7);
    const int bCol = ((lane >> 3) & 1) * 4;

    // staging: 8 threads/row, coalesced 128B rows
    const int sr = t >> 3;        // 0..31
    const int sc = (t & 7) * 4;   // 0..28

    auto stage = [&](int buf, int k0) {
        #pragma unroll
        for (int p = 0; p < 4; p++) {
            const int r = p * 32 + sr;
            float4 av = *reinterpret_cast<const float4*>(
                g_O + (size_t)(m0 + r) * DMODEL + k0 + sc);
            CVT4((&sA[buf][r][sc]), av);
        }
        #pragma unroll
        for (int p = 0; p < 8; p++) {
            const int r = p * 32 + sr;
            float4 wv = *reinterpret_cast<const float4*>(
                W + (size_t)(n0 + r) * DMODEL + k0 + sc);
            CVT4((&sB[buf][r][sc]), wv);
        }
    };

    float acc[4][8][4] = {};

    stage(0, 0);
    __syncthreads();

    const int NITER = DMODEL / PBK;   // 32
    for (int i = 0; i < NITER; i++) {
        const int buf = i & 1;
        if (i + 1 < NITER) stage(buf ^ 1, (i + 1) * PBK);

        #pragma unroll
        for (int kk = 0; kk < PBK; kk += 8) {
            uint32_t a[4][4];
            #pragma unroll
            for (int mt = 0; mt < 4; mt++)
                ldsm_x4(a[mt][0], a[mt][1], a[mt][2], a[mt][3],
                        &sA[buf][wm + mt * 16 + aRow][kk + aCol]);

            uint32_t bf[8][2];
            #pragma unroll
            for (int np = 0; np < 4; np++)
                ldsm_x4(bf[np * 2][0], bf[np * 2][1], bf[np * 2 + 1][0], bf[np * 2 + 1][1],
                        &sB[buf][wn + np * 16 + bRow][kk + bCol]);

            #pragma unroll
            for (int nt = 0; nt < 8; nt++)
                #pragma unroll
                for (int mt = 0; mt < 4; mt++)
                    mma_tf32(acc[mt][nt], a[mt][0], a[mt][1], a[mt][2], a[mt][3],
                             bf[nt][0], bf[nt][1]);
        }
        __syncthreads();
    }

    // ---- epilogue with bias ----
    #pragma unroll
    for (int mt = 0; mt < 4; mt++) {
        const int row = m0 + wm + mt * 16 + g;
        #pragma unroll
        for (int nt = 0; nt < 8; nt++) {
            const int col = n0 + wn + nt * 8 + 2 * tig;
            const float b0v = bias[col], b1v = bias[col + 1];
            *reinterpret_cast<float2*>(out + (size_t)row * DMODEL + col) =
                make_float2(acc[mt][nt][0] + b0v, acc[mt][nt][1] + b1v);
            *reinterpret_cast<float2*>(out + (size_t)(row + 8) * DMODEL + col) =
                make_float2(acc[mt][nt][2] + b0v, acc[mt][nt][3] + b1v);
        }
    }
}

// ---------------------------------------------------------------------------
extern "C" void kernel_launch(void* const* d_in, const int* in_sizes, int n_in,
                              void* d_out, int out_size)
{
    const float* Q  = (const float*)d_in[0];
    const float* K  = (const float*)d_in[1];
    const float* V  = (const float*)d_in[2];
    const float* W  = (const float*)d_in[3];
    const float* bi = (const float*)d_in[4];
    float* out = (float*)d_out;

    cudaFuncSetAttribute(attn_kernel,
                         cudaFuncAttributeMaxDynamicSharedMemorySize, ATTN_SMEM);
    cudaFuncSetAttribute(proj_kernel,
                         cudaFuncAttributeMaxDynamicSharedMemorySize, PROJ_SMEM);

    dim3 agrid(LEN / TQ, HEADS, BATCH);
    attn_kernel<<<agrid, 128, ATTN_SMEM>>>(Q, K, V);

    dim3 pgrid(DMODEL / 256, (BATCH * LEN) / 128);
    proj_kernel<<<pgrid, 256, PROJ_SMEM>>>(W, bi, out);
}

// round 7
// speedup vs baseline: 35.8562x; 1.6087x over previous
#include <cuda_runtime.h>
#include <cuda_fp16.h>
#include <math_constants.h>
#include <cstdint>

// Problem constants
#define BATCH  4
#define LEN    1024
#define DMODEL 1024
#define HEADS  16
#define HDIM   64
// scale * log2(e):  (1/32) * 1.4426950408889634
#define SL2E   0.04508422002778011f

// Attention: 128 q-rows per block, 4 warps x 32 rows, K/V tile 32, dbl-buffered
#define TQ 128
#define TK 32
#define NT (LEN / TK)
// half-unit offsets: sK 2*32*72=4608 | sV 4608 | sP 128*40=5120
#define A_SK 0
#define A_SV 4608
#define A_SP 9216
#define ATTN_SMEM ((9216 + 128 * 40) * 2)     // 28672 bytes

// Projection: 128x128 tile, BK=32, 8 warps (2m x 4n), warp tile 64x32
#define PBK 32
#define PROJ_SMEM (2 * 2 * 128 * 40 * 2)      // 40960 bytes

__device__ float g_O[BATCH * LEN * DMODEL];

// ---- helpers -------------------------------------------------------------

__device__ __forceinline__ float ex2f(float x) {
    float y;
    asm("ex2.approx.ftz.f32 %0, %1;" : "=f"(y) : "f"(x));
    return y;
}

// D = A(16x16,row) * B(16x8,col) + D, fp16 inputs, f32 accum
__device__ __forceinline__ void mma_f16(float c[4],
                                        uint32_t a0, uint32_t a1, uint32_t a2, uint32_t a3,
                                        uint32_t b0, uint32_t b1) {
    asm volatile(
        "mma.sync.aligned.m16n8k16.row.col.f32.f16.f16.f32 "
        "{%0,%1,%2,%3}, {%4,%5,%6,%7}, {%8,%9}, {%0,%1,%2,%3};"
        : "+f"(c[0]), "+f"(c[1]), "+f"(c[2]), "+f"(c[3])
        : "r"(a0), "r"(a1), "r"(a2), "r"(a3), "r"(b0), "r"(b1));
}

__device__ __forceinline__ void ldsm_x4(uint32_t& r0, uint32_t& r1,
                                        uint32_t& r2, uint32_t& r3,
                                        const __half* p) {
    uint32_t addr = (uint32_t)__cvta_generic_to_shared(p);
    asm volatile("ldmatrix.sync.aligned.m8n8.x4.shared.b16 {%0,%1,%2,%3}, [%4];"
                 : "=r"(r0), "=r"(r1), "=r"(r2), "=r"(r3) : "r"(addr));
}
__device__ __forceinline__ void ldsm_x4t(uint32_t& r0, uint32_t& r1,
                                         uint32_t& r2, uint32_t& r3,
                                         const __half* p) {
    uint32_t addr = (uint32_t)__cvta_generic_to_shared(p);
    asm volatile("ldmatrix.sync.aligned.m8n8.x4.trans.shared.b16 {%0,%1,%2,%3}, [%4];"
                 : "=r"(r0), "=r"(r1), "=r"(r2), "=r"(r3) : "r"(addr));
}

#define CVTH4(dst, v4)                                              \
    {   __half2* _d = reinterpret_cast<__half2*>(dst);              \
        _d[0] = __floats2half2_rn(v4.x, v4.y);                      \
        _d[1] = __floats2half2_rn(v4.z, v4.w);  }

extern __shared__ __half dsm[];

// ---------------------------------------------------------------------------
// Flash-style attention, fp16 MMA (m16n8k16). Block = (b,h,128 q rows),
// 4 warps x 32 rows. Q register-resident, max-free softmax, dbl-buffered K/V.
// ---------------------------------------------------------------------------
__global__ __launch_bounds__(128)
void attn_kernel(const float* __restrict__ Q,
                 const float* __restrict__ K,
                 const float* __restrict__ V)
{
    __half (*sK)[TK][72] = reinterpret_cast<__half(*)[TK][72]>(dsm + A_SK);
    __half (*sV)[TK][72] = reinterpret_cast<__half(*)[TK][72]>(dsm + A_SV);
    __half (*sP)[40]     = reinterpret_cast<__half(*)[40]>(dsm + A_SP);

    const int t    = threadIdx.x;
    const int lane = t & 31;
    const int wid  = t >> 5;
    const int g    = lane >> 2;
    const int tig  = lane & 3;
    const int warpM = wid * 32;

    const int b  = blockIdx.z;
    const int h  = blockIdx.y;
    const int q0 = blockIdx.x * TQ;
    const size_t base = (size_t)b * LEN * DMODEL + (size_t)h * HDIM;

    // ldmatrix lane address components
    const int aRow = ((lane >> 3) & 1) * 8 + (lane & 7);   // A frags (Q, P) + V trans
    const int aCol = ((lane >> 4) & 1) * 8;
    const int bRow = ((lane >> 4) & 1) * 8 + (lane & 7);   // K B-frag pairs
    const int bCol = ((lane >> 3) & 1) * 8;

    // ---- stage Q (fp16) into tmp smem (aliases sK+sV), lift to registers ----
    __half (*tmpQ)[72] = reinterpret_cast<__half(*)[72]>(dsm);  // [128][72]
    {
        const int c = (t & 15) * 4;
        #pragma unroll
        for (int p = 0; p < 16; p++) {
            const int r = p * 8 + (t >> 4);
            float4 v4 = *reinterpret_cast<const float4*>(
                Q + base + (size_t)(q0 + r) * DMODEL + c);
            CVTH4((&tmpQ[r][c]), v4);
        }
    }
    __syncthreads();

    uint32_t qf[2][4][4];
    #pragma unroll
    for (int mt = 0; mt < 2; mt++)
        #pragma unroll
        for (int ks = 0; ks < 4; ks++)
            ldsm_x4(qf[mt][ks][0], qf[mt][ks][1], qf[mt][ks][2], qf[mt][ks][3],
                    &tmpQ[warpM + mt * 16 + aRow][ks * 16 + aCol]);
    __syncthreads();

    float o[2][8][4] = {};
    float ls[2][2] = {{0.f, 0.f}, {0.f, 0.f}};

    // K/V staging: 16 threads/row, 4 passes
    const int sc = (t & 15) * 4;
    auto stage = [&](int buf, int kt) {
        #pragma unroll
        for (int p = 0; p < 4; p++) {
            const int r = p * 8 + (t >> 4);
            const size_t go = base + (size_t)(kt * TK + r) * DMODEL + sc;
            float4 kv = *reinterpret_cast<const float4*>(K + go);
            CVTH4((&sK[buf][r][sc]), kv);
            float4 vv = *reinterpret_cast<const float4*>(V + go);
            CVTH4((&sV[buf][r][sc]), vv);
        }
    };

    stage(0, 0);
    __syncthreads();

    for (int kt = 0; kt < NT; kt++) {
        const int buf = kt & 1;
        if (kt + 1 < NT) stage(buf ^ 1, kt + 1);

        // ---- S = Q K^T : 2 mt x 4 nt x 4 k16-steps ----
        float s[2][4][4] = {};
        #pragma unroll
        for (int ks = 0; ks < 4; ks++) {
            uint32_t b00, b01, b10, b11;
            ldsm_x4(b00, b01, b10, b11, &sK[buf][bRow][ks * 16 + bCol]);        // nt 0,1
            uint32_t b20, b21, b30, b31;
            ldsm_x4(b20, b21, b30, b31, &sK[buf][16 + bRow][ks * 16 + bCol]);   // nt 2,3
            #pragma unroll
            for (int mt = 0; mt < 2; mt++) {
                mma_f16(s[mt][0], qf[mt][ks][0], qf[mt][ks][1], qf[mt][ks][2], qf[mt][ks][3], b00, b01);
                mma_f16(s[mt][1], qf[mt][ks][0], qf[mt][ks][1], qf[mt][ks][2], qf[mt][ks][3], b10, b11);
                mma_f16(s[mt][2], qf[mt][ks][0], qf[mt][ks][1], qf[mt][ks][2], qf[mt][ks][3], b20, b21);
                mma_f16(s[mt][3], qf[mt][ks][0], qf[mt][ks][1], qf[mt][ks][2], qf[mt][ks][3], b30, b31);
            }
        }

        // ---- max-free softmax: p = 2^(s*SL2E), store fp16 P ----
        #pragma unroll
        for (int mt = 0; mt < 2; mt++)
            #pragma unroll
            for (int nt = 0; nt < 4; nt++) {
                float p00 = ex2f(s[mt][nt][0] * SL2E);
                float p01 = ex2f(s[mt][nt][1] * SL2E);
                float p10 = ex2f(s[mt][nt][2] * SL2E);
                float p11 = ex2f(s[mt][nt][3] * SL2E);
                ls[mt][0] += p00 + p01;
                ls[mt][1] += p10 + p11;
                *reinterpret_cast<__half2*>(&sP[warpM + mt * 16 + g    ][nt * 8 + 2 * tig]) =
                    __floats2half2_rn(p00, p01);
                *reinterpret_cast<__half2*>(&sP[warpM + mt * 16 + g + 8][nt * 8 + 2 * tig]) =
                    __floats2half2_rn(p10, p11);
            }
        __syncwarp();

        // ---- O += P V : A from sP (ldsm), B from sV (ldsm trans) ----
        #pragma unroll
        for (int k0 = 0; k0 < TK; k0 += 16) {
            uint32_t a[2][4];
            #pragma unroll
            for (int mt = 0; mt < 2; mt++)
                ldsm_x4(a[mt][0], a[mt][1], a[mt][2], a[mt][3],
                        &sP[warpM + mt * 16 + aRow][k0 + aCol]);
            #pragma unroll
            for (int j = 0; j < 4; j++) {
                uint32_t v0, v1, v2, v3;
                ldsm_x4t(v0, v1, v2, v3, &sV[buf][k0 + aRow][j * 16 + aCol]);
                mma_f16(o[0][2 * j    ], a[0][0], a[0][1], a[0][2], a[0][3], v0, v1);
                mma_f16(o[1][2 * j    ], a[1][0], a[1][1], a[1][2], a[1][3], v0, v1);
                mma_f16(o[0][2 * j + 1], a[0][0], a[0][1], a[0][2], a[0][3], v2, v3);
                mma_f16(o[1][2 * j + 1], a[1][0], a[1][1], a[1][2], a[1][3], v2, v3);
            }
        }
        __syncthreads();
    }

    // ---- final row-sum reduce, write ----
    #pragma unroll
    for (int mt = 0; mt < 2; mt++) {
        ls[mt][0] += __shfl_xor_sync(0xffffffffu, ls[mt][0], 1);
        ls[mt][0] += __shfl_xor_sync(0xffffffffu, ls[mt][0], 2);
        ls[mt][1] += __shfl_xor_sync(0xffffffffu, ls[mt][1], 1);
        ls[mt][1] += __shfl_xor_sync(0xffffffffu, ls[mt][1], 2);
        const float inv0 = 1.0f / ls[mt][0], inv1 = 1.0f / ls[mt][1];
        #pragma unroll
        for (int nt = 0; nt < 8; nt++) {
            const int col = nt * 8 + 2 * tig;
            *reinterpret_cast<float2*>(
                &g_O[base + (size_t)(q0 + warpM + mt * 16 + g) * DMODEL + col]) =
                make_float2(o[mt][nt][0] * inv0, o[mt][nt][1] * inv0);
            *reinterpret_cast<float2*>(
                &g_O[base + (size_t)(q0 + warpM + mt * 16 + g + 8) * DMODEL + col]) =
                make_float2(o[mt][nt][2] * inv1, o[mt][nt][3] * inv1);
        }
    }
}

// ---------------------------------------------------------------------------
// Projection: out = g_O @ W^T + bias, fp16 MMA. 128x128 tile, BK=32,
// 8 warps (2m x 4n), warp tile 64x32, double-buffered, 2 CTAs/SM.
// ---------------------------------------------------------------------------
__global__ __launch_bounds__(256, 2)
void proj_kernel(const float* __restrict__ W,
                 const float* __restrict__ bias,
                 float* __restrict__ out)
{
    __half (*sA)[128][40] = reinterpret_cast<__half(*)[128][40]>(dsm);
    __half (*sB)[128][40] = reinterpret_cast<__half(*)[128][40]>(dsm + 2 * 128 * 40);

    const int t    = threadIdx.x;
    const int lane = t & 31;
    const int wid  = t >> 5;
    const int g    = lane >> 2;
    const int tig  = lane & 3;
    const int wm   = (wid >> 2) * 64;
    const int wn   = (wid & 3) * 32;
    const int m0   = blockIdx.y * 128;
    const int n0   = blockIdx.x * 128;

    const int aRow = ((lane >> 3) & 1) * 8 + (lane & 7);
    const int aCol = ((lane >> 4) & 1) * 8;
    const int bRow = ((lane >> 4) & 1) * 8 + (lane & 7);
    const int bCol = ((lane >> 3) & 1) * 8;

    const int sr = t >> 3;        // 0..31
    const int sc = (t & 7) * 4;   // 0..28

    auto stage = [&](int buf, int k0) {
        #pragma unroll
        for (int p = 0; p < 4; p++) {
            const int r = p * 32 + sr;
            float4 av = *reinterpret_cast<const float4*>(
                g_O + (size_t)(m0 + r) * DMODEL + k0 + sc);
            CVTH4((&sA[buf][r][sc]), av);
            float4 wv = *reinterpret_cast<const float4*>(
                W + (size_t)(n0 + r) * DMODEL + k0 + sc);
            CVTH4((&sB[buf][r][sc]), wv);
        }
    };

    float acc[4][4][4] = {};

    stage(0, 0);
    __syncthreads();

    const int NITER = DMODEL / PBK;   // 32
    for (int i = 0; i < NITER; i++) {
        const int buf = i & 1;
        if (i + 1 < NITER) stage(buf ^ 1, (i + 1) * PBK);

        #pragma unroll
        for (int kk = 0; kk < PBK; kk += 16) {
            uint32_t a[4][4];
            #pragma unroll
            for (int mt = 0; mt < 4; mt++)
                ldsm_x4(a[mt][0], a[mt][1], a[mt][2], a[mt][3],
                        &sA[buf][wm + mt * 16 + aRow][kk + aCol]);

            uint32_t bf[4][2];
            #pragma unroll
            for (int np = 0; np < 2; np++)
                ldsm_x4(bf[np * 2][0], bf[np * 2][1], bf[np * 2 + 1][0], bf[np * 2 + 1][1],
                        &sB[buf][wn + np * 16 + bRow][kk + bCol]);

            #pragma unroll
            for (int nt = 0; nt < 4; nt++)
                #pragma unroll
                for (int mt = 0; mt < 4; mt++)
                    mma_f16(acc[mt][nt], a[mt][0], a[mt][1], a[mt][2], a[mt][3],
                            bf[nt][0], bf[nt][1]);
        }
        __syncthreads();
    }

    // ---- epilogue with bias ----
    #pragma unroll
    for (int mt = 0; mt < 4; mt++) {
        const int row = m0 + wm + mt * 16 + g;
        #pragma unroll
        for (int nt = 0; nt < 4; nt++) {
            const int col = n0 + wn + nt * 8 + 2 * tig;
            const float b0v = bias[col], b1v = bias[col + 1];
            *reinterpret_cast<float2*>(out + (size_t)row * DMODEL + col) =
                make_float2(acc[mt][nt][0] + b0v, acc[mt][nt][1] + b1v);
            *reinterpret_cast<float2*>(out + (size_t)(row + 8) * DMODEL + col) =
                make_float2(acc[mt][nt][2] + b0v, acc[mt][nt][3] + b1v);
        }
    }
}

// ---------------------------------------------------------------------------
extern "C" void kernel_launch(void* const* d_in, const int* in_sizes, int n_in,
                              void* d_out, int out_size)
{
    const float* Q  = (const float*)d_in[0];
    const float* K  = (const float*)d_in[1];
    const float* V  = (const float*)d_in[2];
    const float* W  = (const float*)d_in[3];
    const float* bi = (const float*)d_in[4];
    float* out = (float*)d_out;

    cudaFuncSetAttribute(attn_kernel,
                         cudaFuncAttributeMaxDynamicSharedMemorySize, ATTN_SMEM);
    cudaFuncSetAttribute(proj_kernel,
                         cudaFuncAttributeMaxDynamicSharedMemorySize, PROJ_SMEM);

    dim3 agrid(LEN / TQ, HEADS, BATCH);
    attn_kernel<<<agrid, 128, ATTN_SMEM>>>(Q, K, V);

    dim3 pgrid(DMODEL / 128, (BATCH * LEN) / 128);
    proj_kernel<<<pgrid, 256, PROJ_SMEM>>>(W, bi, out);
}

// round 8
// speedup vs baseline: 48.0089x; 1.3389x over previous
#include <cuda_runtime.h>
#include <cuda_fp16.h>
#include <math_constants.h>
#include <cstdint>

// Problem constants
#define BATCH  4
#define LEN    1024
#define DMODEL 1024
#define HEADS  16
#define HDIM   64
// scale * log2(e):  (1/32) * 1.4426950408889634
#define SL2E   0.04508422002778011f

#define NK (BATCH * LEN * DMODEL)     // 4194304
#define NW (DMODEL * DMODEL)          // 1048576

// Attention: 128 q-rows per block, 4 warps x 32 rows, K/V tile 32, 3-stage pipe
#define TQ 128
#define TK 32
#define NT (LEN / TK)
// half-unit offsets
#define A_SK 0                        // 3*32*72  = 6912
#define A_SV 6912                     // 3*32*72  = 6912
#define A_SP 13824                    // 128*40   = 5120
#define ATTN_SMEM ((13824 + 5120) * 2)   // 37888 B

// Projection: 128x128 tile, BK=32, 8 warps (2m x 4n), warp tile 64x32, 3-stage
#define PBK 32
#define P_SB 15360                    // 3*128*40 = 15360 halves each
#define PROJ_SMEM (2 * 15360 * 2)     // 61440 B

// fp16 mirrors (device globals; allocs forbidden)
__device__ __half g_K16[NK];
__device__ __half g_V16[NK];
__device__ __half g_W16[NW];
__device__ __half g_O16[NK];

// ---- helpers -------------------------------------------------------------

__device__ __forceinline__ float ex2f(float x) {
    float y;
    asm("ex2.approx.ftz.f32 %0, %1;" : "=f"(y) : "f"(x));
    return y;
}

__device__ __forceinline__ void mma_f16(float c[4],
                                        uint32_t a0, uint32_t a1, uint32_t a2, uint32_t a3,
                                        uint32_t b0, uint32_t b1) {
    asm volatile(
        "mma.sync.aligned.m16n8k16.row.col.f32.f16.f16.f32 "
        "{%0,%1,%2,%3}, {%4,%5,%6,%7}, {%8,%9}, {%0,%1,%2,%3};"
        : "+f"(c[0]), "+f"(c[1]), "+f"(c[2]), "+f"(c[3])
        : "r"(a0), "r"(a1), "r"(a2), "r"(a3), "r"(b0), "r"(b1));
}

__device__ __forceinline__ void ldsm_x4(uint32_t& r0, uint32_t& r1,
                                        uint32_t& r2, uint32_t& r3,
                                        const __half* p) {
    uint32_t addr = (uint32_t)__cvta_generic_to_shared(p);
    asm volatile("ldmatrix.sync.aligned.m8n8.x4.shared.b16 {%0,%1,%2,%3}, [%4];"
                 : "=r"(r0), "=r"(r1), "=r"(r2), "=r"(r3) : "r"(addr));
}
__device__ __forceinline__ void ldsm_x4t(uint32_t& r0, uint32_t& r1,
                                         uint32_t& r2, uint32_t& r3,
                                         const __half* p) {
    uint32_t addr = (uint32_t)__cvta_generic_to_shared(p);
    asm volatile("ldmatrix.sync.aligned.m8n8.x4.trans.shared.b16 {%0,%1,%2,%3}, [%4];"
                 : "=r"(r0), "=r"(r1), "=r"(r2), "=r"(r3) : "r"(addr));
}

__device__ __forceinline__ void cp16(__half* sdst, const __half* gsrc) {
    uint32_t d = (uint32_t)__cvta_generic_to_shared(sdst);
    asm volatile("cp.async.cg.shared.global [%0], [%1], 16;" :: "r"(d), "l"(gsrc));
}
#define CP_COMMIT() asm volatile("cp.async.commit_group;")
#define CP_WAIT1()  asm volatile("cp.async.wait_group 1;")

#define CVTH4(dst, v4)                                              \
    {   __half2* _d = reinterpret_cast<__half2*>(dst);              \
        _d[0] = __floats2half2_rn(v4.x, v4.y);                      \
        _d[1] = __floats2half2_rn(v4.z, v4.w);  }

extern __shared__ __half dsm[];

// ---------------------------------------------------------------------------
// fp32 -> fp16 pre-conversion for K, V, W (8 elems / thread)
// ---------------------------------------------------------------------------
__global__ __launch_bounds__(256)
void cvt16_kernel(const float* __restrict__ K,
                  const float* __restrict__ V,
                  const float* __restrict__ W)
{
    const size_t i = ((size_t)blockIdx.x * 256 + threadIdx.x) * 8;
    const float* src;
    __half* dst;
    size_t off;
    if (i < NK)            { src = K; dst = g_K16; off = i; }
    else if (i < 2 * (size_t)NK) { src = V; dst = g_V16; off = i - NK; }
    else {
        off = i - 2 * (size_t)NK;
        if (off >= NW) return;
        src = W; dst = g_W16;
    }
    float4 a = *reinterpret_cast<const float4*>(src + off);
    float4 b = *reinterpret_cast<const float4*>(src + off + 4);
    __half2 h[4] = { __floats2half2_rn(a.x, a.y), __floats2half2_rn(a.z, a.w),
                     __floats2half2_rn(b.x, b.y), __floats2half2_rn(b.z, b.w) };
    *reinterpret_cast<uint4*>(dst + off) = *reinterpret_cast<uint4*>(h);
}

// ---------------------------------------------------------------------------
// Flash-style attention, fp16 MMA, cp.async 3-stage K/V pipeline.
// Block = (b,h,128 q rows), 4 warps x 32 rows. Q register-resident.
// ---------------------------------------------------------------------------
__global__ __launch_bounds__(128)
void attn_kernel(const float* __restrict__ Q)
{
    __half (*sK)[TK][72] = reinterpret_cast<__half(*)[TK][72]>(dsm + A_SK);
    __half (*sV)[TK][72] = reinterpret_cast<__half(*)[TK][72]>(dsm + A_SV);
    __half (*sP)[40]     = reinterpret_cast<__half(*)[40]>(dsm + A_SP);

    const int t    = threadIdx.x;
    const int lane = t & 31;
    const int wid  = t >> 5;
    const int g    = lane >> 2;
    const int tig  = lane & 3;
    const int warpM = wid * 32;

    const int b  = blockIdx.z;
    const int h  = blockIdx.y;
    const int q0 = blockIdx.x * TQ;
    const size_t base = (size_t)b * LEN * DMODEL + (size_t)h * HDIM;

    const int aRow = ((lane >> 3) & 1) * 8 + (lane & 7);   // A frags (Q, P) + V trans
    const int aCol = ((lane >> 4) & 1) * 8;
    const int bRow = ((lane >> 4) & 1) * 8 + (lane & 7);   // K B-frag pairs
    const int bCol = ((lane >> 3) & 1) * 8;

    // ---- stage Q (f32 -> fp16) into tmp smem, lift fragments to registers ----
    __half (*tmpQ)[72] = reinterpret_cast<__half(*)[72]>(dsm);  // [128][72]
    {
        const int c = (t & 15) * 4;
        #pragma unroll
        for (int p = 0; p < 16; p++) {
            const int r = p * 8 + (t >> 4);
            float4 v4 = *reinterpret_cast<const float4*>(
                Q + base + (size_t)(q0 + r) * DMODEL + c);
            CVTH4((&tmpQ[r][c]), v4);
        }
    }
    __syncthreads();

    uint32_t qf[2][4][4];
    #pragma unroll
    for (int mt = 0; mt < 2; mt++)
        #pragma unroll
        for (int ks = 0; ks < 4; ks++)
            ldsm_x4(qf[mt][ks][0], qf[mt][ks][1], qf[mt][ks][2], qf[mt][ks][3],
                    &tmpQ[warpM + mt * 16 + aRow][ks * 16 + aCol]);
    __syncthreads();   // tmpQ dead; sK/sV region free for cp.async

    float o[2][8][4] = {};
    float ls[2][2] = {{0.f, 0.f}, {0.f, 0.f}};

    // cp.async staging: 4 threads/row, 2x16B each
    const int sr = t >> 2;          // 0..31
    const int sq = (t & 3) * 16;    // half offset
    auto stage = [&](int buf, int kt) {
        const __half* kp = g_K16 + base + (size_t)(kt * TK + sr) * DMODEL + sq;
        const __half* vp = g_V16 + base + (size_t)(kt * TK + sr) * DMODEL + sq;
        cp16(&sK[buf][sr][sq], kp);
        cp16(&sK[buf][sr][sq + 8], kp + 8);
        cp16(&sV[buf][sr][sq], vp);
        cp16(&sV[buf][sr][sq + 8], vp + 8);
    };

    stage(0, 0); CP_COMMIT();
    stage(1, 1); CP_COMMIT();

    for (int kt = 0; kt < NT; kt++) {
        CP_WAIT1();
        __syncthreads();
        if (kt + 2 < NT) stage((kt + 2) % 3, kt + 2);
        CP_COMMIT();

        const int buf = kt % 3;

        // ---- S = Q K^T : 2 mt x 4 nt x 4 k16-steps ----
        float s[2][4][4] = {};
        #pragma unroll
        for (int ks = 0; ks < 4; ks++) {
            uint32_t b00, b01, b10, b11;
            ldsm_x4(b00, b01, b10, b11, &sK[buf][bRow][ks * 16 + bCol]);
            uint32_t b20, b21, b30, b31;
            ldsm_x4(b20, b21, b30, b31, &sK[buf][16 + bRow][ks * 16 + bCol]);
            #pragma unroll
            for (int mt = 0; mt < 2; mt++) {
                mma_f16(s[mt][0], qf[mt][ks][0], qf[mt][ks][1], qf[mt][ks][2], qf[mt][ks][3], b00, b01);
                mma_f16(s[mt][1], qf[mt][ks][0], qf[mt][ks][1], qf[mt][ks][2], qf[mt][ks][3], b10, b11);
                mma_f16(s[mt][2], qf[mt][ks][0], qf[mt][ks][1], qf[mt][ks][2], qf[mt][ks][3], b20, b21);
                mma_f16(s[mt][3], qf[mt][ks][0], qf[mt][ks][1], qf[mt][ks][2], qf[mt][ks][3], b30, b31);
            }
        }

        // ---- max-free softmax: p = 2^(s*SL2E), store fp16 P ----
        #pragma unroll
        for (int mt = 0; mt < 2; mt++)
            #pragma unroll
            for (int nt = 0; nt < 4; nt++) {
                float p00 = ex2f(s[mt][nt][0] * SL2E);
                float p01 = ex2f(s[mt][nt][1] * SL2E);
                float p10 = ex2f(s[mt][nt][2] * SL2E);
                float p11 = ex2f(s[mt][nt][3] * SL2E);
                ls[mt][0] += p00 + p01;
                ls[mt][1] += p10 + p11;
                *reinterpret_cast<__half2*>(&sP[warpM + mt * 16 + g    ][nt * 8 + 2 * tig]) =
                    __floats2half2_rn(p00, p01);
                *reinterpret_cast<__half2*>(&sP[warpM + mt * 16 + g + 8][nt * 8 + 2 * tig]) =
                    __floats2half2_rn(p10, p11);
            }
        __syncwarp();

        // ---- O += P V ----
        #pragma unroll
        for (int k0 = 0; k0 < TK; k0 += 16) {
            uint32_t a[2][4];
            #pragma unroll
            for (int mt = 0; mt < 2; mt++)
                ldsm_x4(a[mt][0], a[mt][1], a[mt][2], a[mt][3],
                        &sP[warpM + mt * 16 + aRow][k0 + aCol]);
            #pragma unroll
            for (int j = 0; j < 4; j++) {
                uint32_t v0, v1, v2, v3;
                ldsm_x4t(v0, v1, v2, v3, &sV[buf][k0 + aRow][j * 16 + aCol]);
                mma_f16(o[0][2 * j    ], a[0][0], a[0][1], a[0][2], a[0][3], v0, v1);
                mma_f16(o[1][2 * j    ], a[1][0], a[1][1], a[1][2], a[1][3], v0, v1);
                mma_f16(o[0][2 * j + 1], a[0][0], a[0][1], a[0][2], a[0][3], v2, v3);
                mma_f16(o[1][2 * j + 1], a[1][0], a[1][1], a[1][2], a[1][3], v2, v3);
            }
        }
    }

    // ---- final row-sum reduce, write fp16 output ----
    #pragma unroll
    for (int mt = 0; mt < 2; mt++) {
        ls[mt][0] += __shfl_xor_sync(0xffffffffu, ls[mt][0], 1);
        ls[mt][0] += __shfl_xor_sync(0xffffffffu, ls[mt][0], 2);
        ls[mt][1] += __shfl_xor_sync(0xffffffffu, ls[mt][1], 1);
        ls[mt][1] += __shfl_xor_sync(0xffffffffu, ls[mt][1], 2);
        const float inv0 = 1.0f / ls[mt][0], inv1 = 1.0f / ls[mt][1];
        #pragma unroll
        for (int nt = 0; nt < 8; nt++) {
            const int col = nt * 8 + 2 * tig;
            *reinterpret_cast<__half2*>(
                &g_O16[base + (size_t)(q0 + warpM + mt * 16 + g) * DMODEL + col]) =
                __floats2half2_rn(o[mt][nt][0] * inv0, o[mt][nt][1] * inv0);
            *reinterpret_cast<__half2*>(
                &g_O16[base + (size_t)(q0 + warpM + mt * 16 + g + 8) * DMODEL + col]) =
                __floats2half2_rn(o[mt][nt][2] * inv1, o[mt][nt][3] * inv1);
        }
    }
}

// ---------------------------------------------------------------------------
// Projection: out = g_O16 @ g_W16^T + bias, fp16 MMA, cp.async 3-stage pipe.
// 128x128 tile, BK=32, 8 warps (2m x 4n), warp tile 64x32, 2 CTAs/SM.
// ---------------------------------------------------------------------------
__global__ __launch_bounds__(256, 2)
void proj_kernel(const float* __restrict__ bias,
                 float* __restrict__ out)
{
    __half (*sA)[128][40] = reinterpret_cast<__half(*)[128][40]>(dsm);
    __half (*sB)[128][40] = reinterpret_cast<__half(*)[128][40]>(dsm + P_SB);

    const int t    = threadIdx.x;
    const int lane = t & 31;
    const int wid  = t >> 5;
    const int g    = lane >> 2;
    const int tig  = lane & 3;
    const int wm   = (wid >> 2) * 64;
    const int wn   = (wid & 3) * 32;
    const int m0   = blockIdx.y * 128;
    const int n0   = blockIdx.x * 128;

    const int aRow = ((lane >> 3) & 1) * 8 + (lane & 7);
    const int aCol = ((lane >> 4) & 1) * 8;
    const int bRow = ((lane >> 4) & 1) * 8 + (lane & 7);
    const int bCol = ((lane >> 3) & 1) * 8;

    // cp.async staging: 2 threads/row, 2x16B each
    const int sr = t >> 1;          // 0..127
    const int sq = (t & 1) * 16;    // half offset
    auto stage = [&](int buf, int k0) {
        const __half* ap = g_O16 + (size_t)(m0 + sr) * DMODEL + k0 + sq;
        const __half* bp = g_W16 + (size_t)(n0 + sr) * DMODEL + k0 + sq;
        cp16(&sA[buf][sr][sq], ap);
        cp16(&sA[buf][sr][sq + 8], ap + 8);
        cp16(&sB[buf][sr][sq], bp);
        cp16(&sB[buf][sr][sq + 8], bp + 8);
    };

    float acc[4][4][4] = {};

    stage(0, 0);      CP_COMMIT();
    stage(1, PBK);    CP_COMMIT();

    const int NITER = DMODEL / PBK;   // 32
    for (int i = 0; i < NITER; i++) {
        CP_WAIT1();
        __syncthreads();
        if (i + 2 < NITER) stage((i + 2) % 3, (i + 2) * PBK);
        CP_COMMIT();

        const int buf = i % 3;

        #pragma unroll
        for (int kk = 0; kk < PBK; kk += 16) {
            uint32_t a[4][4];
            #pragma unroll
            for (int mt = 0; mt < 4; mt++)
                ldsm_x4(a[mt][0], a[mt][1], a[mt][2], a[mt][3],
                        &sA[buf][wm + mt * 16 + aRow][kk + aCol]);

            uint32_t bf[4][2];
            #pragma unroll
            for (int np = 0; np < 2; np++)
                ldsm_x4(bf[np * 2][0], bf[np * 2][1], bf[np * 2 + 1][0], bf[np * 2 + 1][1],
                        &sB[buf][wn + np * 16 + bRow][kk + bCol]);

            #pragma unroll
            for (int nt = 0; nt < 4; nt++)
                #pragma unroll
                for (int mt = 0; mt < 4; mt++)
                    mma_f16(acc[mt][nt], a[mt][0], a[mt][1], a[mt][2], a[mt][3],
                            bf[nt][0], bf[nt][1]);
        }
    }

    // ---- epilogue with bias ----
    #pragma unroll
    for (int mt = 0; mt < 4; mt++) {
        const int row = m0 + wm + mt * 16 + g;
        #pragma unroll
        for (int nt = 0; nt < 4; nt++) {
            const int col = n0 + wn + nt * 8 + 2 * tig;
            const float b0v = bias[col], b1v = bias[col + 1];
            *reinterpret_cast<float2*>(out + (size_t)row * DMODEL + col) =
                make_float2(acc[mt][nt][0] + b0v, acc[mt][nt][1] + b1v);
            *reinterpret_cast<float2*>(out + (size_t)(row + 8) * DMODEL + col) =
                make_float2(acc[mt][nt][2] + b0v, acc[mt][nt][3] + b1v);
        }
    }
}

// ---------------------------------------------------------------------------
extern "C" void kernel_launch(void* const* d_in, const int* in_sizes, int n_in,
                              void* d_out, int out_size)
{
    const float* Q  = (const float*)d_in[0];
    const float* K  = (const float*)d_in[1];
    const float* V  = (const float*)d_in[2];
    const float* W  = (const float*)d_in[3];
    const float* bi = (const float*)d_in[4];
    float* out = (float*)d_out;

    cudaFuncSetAttribute(attn_kernel,
                         cudaFuncAttributeMaxDynamicSharedMemorySize, ATTN_SMEM);
    cudaFuncSetAttribute(proj_kernel,
                         cudaFuncAttributeMaxDynamicSharedMemorySize, PROJ_SMEM);

    const int ncvt = (2 * NK + NW) / 8;      // 1179648 threads
    cvt16_kernel<<<ncvt / 256, 256>>>(K, V, W);

    dim3 agrid(LEN / TQ, HEADS, BATCH);
    attn_kernel<<<agrid, 128, ATTN_SMEM>>>(Q);

    dim3 pgrid(DMODEL / 128, (BATCH * LEN) / 128);
    proj_kernel<<<pgrid, 256, PROJ_SMEM>>>(bi, out);
}